// round 6
// baseline (speedup 1.0000x reference)
#include <cuda_runtime.h>
#include <cuda_bf16.h>
#include <cstdint>
#include <math.h>

// ---------------- problem constants ----------------
#define NN     87381
#define HH     512
#define OUTF   256
#define NLEAF  65536
#define SLEAF  21845
static const int LS[10] = {0,1,5,21,85,341,1365,5461,21845,87381};

// converted weight offsets (elements), all [N,K=512] row-major bf16
#define OFF_WIN    0
#define OFF_IOUX0  262144
#define OFF_IOUX1  1048576
#define OFF_IOUH0  1835008
#define OFF_IOUH1  2621440
#define OFF_FX0    3407872
#define OFF_FX1    3670016
#define OFF_FH0    3932160
#define OFF_FH1    4194304
#define OFF_WOUT   4456448
#define WTOT       4587520

// ---------------- scratch (device globals; no allocation) ----------
__device__ __nv_bfloat16 g_wh[WTOT];
__device__ __nv_bfloat16 g_wl[WTOT];
__device__ __nv_bfloat16 g_xh [(size_t)NN * HH];
__device__ __nv_bfloat16 g_xl [(size_t)NN * HH];
__device__ __nv_bfloat16 g_h0h[(size_t)NN * HH];
__device__ __nv_bfloat16 g_h0l[(size_t)NN * HH];
__device__ __nv_bfloat16 g_hih[(size_t)NN * HH];
__device__ __nv_bfloat16 g_hil[(size_t)NN * HH];
__device__ __nv_bfloat16 g_hsh[(size_t)16384 * HH];
__device__ __nv_bfloat16 g_hsl[(size_t)16384 * HH];
__device__ float g_cell[(size_t)NN * HH];
__device__ float g_iou [(size_t)NLEAF * 1536];
__device__ float g_fx  [(size_t)16384 * HH];
__device__ float g_fh  [(size_t)NLEAF * HH];
__device__ float g_part[(size_t)512 * HH];
__device__ float g_cs  [HH];

// ---------------- portable PTX helpers (sm_80+ only) ----------------
__device__ __forceinline__ void mma16816(float* c, const uint32_t* a, const uint32_t* b) {
    asm volatile(
        "mma.sync.aligned.m16n8k16.row.col.f32.bf16.bf16.f32 "
        "{%0,%1,%2,%3}, {%4,%5,%6,%7}, {%8,%9}, {%0,%1,%2,%3};"
        : "+f"(c[0]), "+f"(c[1]), "+f"(c[2]), "+f"(c[3])
        : "r"(a[0]), "r"(a[1]), "r"(a[2]), "r"(a[3]), "r"(b[0]), "r"(b[1]));
}
__device__ __forceinline__ void ldsm4(uint32_t* r, uint32_t addr) {
    asm volatile("ldmatrix.sync.aligned.m8n8.x4.shared.b16 {%0,%1,%2,%3}, [%4];"
        : "=r"(r[0]), "=r"(r[1]), "=r"(r[2]), "=r"(r[3]) : "r"(addr));
}
__device__ __forceinline__ void cp16z(uint16_t* dst, const void* src, bool pred) {
    uint32_t d = (uint32_t)__cvta_generic_to_shared(dst);
    int sz = pred ? 16 : 0;
    asm volatile("cp.async.cg.shared.global [%0], [%1], 16, %2;" :: "r"(d), "l"(src), "r"(sz));
}
__device__ __forceinline__ void cp_commit() { asm volatile("cp.async.commit_group;" ::: "memory"); }
__device__ __forceinline__ void cp_wait2()  { asm volatile("cp.async.wait_group 2;"  ::: "memory"); }

__device__ __forceinline__ void split2(float a, float b, uint32_t& hi, uint32_t& lo) {
    __nv_bfloat16 h0 = __float2bfloat16(a), h1 = __float2bfloat16(b);
    __nv_bfloat16 l0 = __float2bfloat16(a - __bfloat162float(h0));
    __nv_bfloat16 l1 = __float2bfloat16(b - __bfloat162float(h1));
    hi = (uint32_t)*(uint16_t*)&h0 | ((uint32_t)*(uint16_t*)&h1 << 16);
    lo = (uint32_t)*(uint16_t*)&l0 | ((uint32_t)*(uint16_t*)&l1 << 16);
}

// ---------------- mma.sync GEMM ------------------------------------------
// C = [A1@B1^T (+ A2@B2^T)] (+bias)(+relu). All operands bf16 hi/lo pairs.
// K = 512 per pass. CTA tile 128x128, 8 warps (2m x 4n), warp tile 64x32,
// K chunk 16. 4-stage cp.async pipeline, ONE barrier per chunk.
// Fragment loads via ldmatrix.x4 (12 instr/chunk vs 48 LDS.32). 3-pass split.
#define ASTR 24
#define TE   3072       // 128*24 elems per tile
#define STGE 12288      // 4 tiles per stage (24576 B)

template <bool RELU, bool SPLIT>
__global__ __launch_bounds__(256, 2) void gemm_mma(
    const __nv_bfloat16* __restrict__ A1h, const __nv_bfloat16* __restrict__ A1l,
    const __nv_bfloat16* __restrict__ B1h, const __nv_bfloat16* __restrict__ B1l,
    const __nv_bfloat16* __restrict__ A2h, const __nv_bfloat16* __restrict__ A2l,
    const __nv_bfloat16* __restrict__ B2h, const __nv_bfloat16* __restrict__ B2l,
    const float* __restrict__ bias,
    float* __restrict__ Cf,
    __nv_bfloat16* __restrict__ Ch, __nv_bfloat16* __restrict__ Cl,
    int M, int Ntot)
{
    extern __shared__ uint16_t sm16[];
    const int t    = threadIdx.x;
    const int lane = t & 31, wid = t >> 5;
    const int q = lane >> 2, p = lane & 3;
    const int wm = wid >> 2, wn = wid & 3;       // 2 x 4 warps, tile 64x32
    const int bm = blockIdx.y * 128;
    const int bn = blockIdx.x * 128;

    const int r  = t >> 1;          // staging row 0..127
    const int hf = t & 1;           // 8-elem half

    const int npass = (A2h != nullptr) ? 2 : 1;
    const int CT = npass * 32;

    // ldmatrix per-lane base offsets (bytes), within one tile
    const uint32_t smb = (uint32_t)__cvta_generic_to_shared(sm16);
    const int lrow = lane & 15, lcol = (lane >> 4) * 8;
    uint32_t aoff[4], boff[2];
#pragma unroll
    for (int im = 0; im < 4; ++im)
        aoff[im] = smb + ((wm * 64 + im * 16 + lrow) * ASTR + lcol) * 2;
#pragma unroll
    for (int j = 0; j < 2; ++j)
        boff[j] = smb + ((wn * 32 + j * 16 + lrow) * ASTR + lcol) * 2;

    float acc[4][4][4];
#pragma unroll
    for (int im = 0; im < 4; ++im)
#pragma unroll
        for (int in = 0; in < 4; ++in)
#pragma unroll
            for (int k = 0; k < 4; ++k) acc[im][in][k] = 0.f;

    auto stage = [&](int cc) {
        const int pass = cc >> 5, k0 = (cc & 31) * 16;
        const __nv_bfloat16* Ah = pass ? A2h : A1h;
        const __nv_bfloat16* Al = pass ? A2l : A1l;
        const __nv_bfloat16* Bh = pass ? B2h : B1h;
        const __nv_bfloat16* Bl = pass ? B2l : B1l;
        uint16_t* stg = sm16 + (cc & 3) * STGE;
        const bool pa = (bm + r < M);
        const size_t asrc = (size_t)(bm + r) * 512 + k0 + hf * 8;
        const size_t bsrc = (size_t)(bn + r) * 512 + k0 + hf * 8;
        uint16_t* dst = stg + r * ASTR + hf * 8;
        cp16z(dst,          Ah + asrc, pa);
        cp16z(dst + TE,     Al + asrc, pa);
        cp16z(dst + 2 * TE, Bh + bsrc, true);
        cp16z(dst + 3 * TE, Bl + bsrc, true);
    };

    stage(0); cp_commit();
    if (CT > 1) { stage(1); cp_commit(); }

    for (int c = 0; c < CT; ++c) {
        if (c + 2 < CT) stage(c + 2);
        cp_commit();
        cp_wait2();
        __syncthreads();

        const uint32_t so = (uint32_t)((c & 3) * STGE * 2);  // stage byte offset
        // B fragments: pair j covers in = 2j, 2j+1
        uint32_t bhf[2][4], blf[2][4];
#pragma unroll
        for (int j = 0; j < 2; ++j) {
            ldsm4(bhf[j], boff[j] + so + 2 * TE * 2);
            ldsm4(blf[j], boff[j] + so + 3 * TE * 2);
        }
#pragma unroll
        for (int im = 0; im < 4; ++im) {
            uint32_t ah[4], al[4];
            ldsm4(ah, aoff[im] + so);
            ldsm4(al, aoff[im] + so + TE * 2);
#pragma unroll
            for (int in = 0; in < 4; ++in) {
                const int j = in >> 1, h = in & 1;
                uint32_t bh2[2] = { bhf[j][h], bhf[j][h + 2] };
                uint32_t bl2[2] = { blf[j][h], blf[j][h + 2] };
                mma16816(acc[im][in], ah, bh2);
                mma16816(acc[im][in], ah, bl2);
                mma16816(acc[im][in], al, bh2);
            }
        }
    }

    // ---- epilogue
#pragma unroll
    for (int im = 0; im < 4; ++im) {
#pragma unroll
        for (int in = 0; in < 4; ++in) {
            int row = bm + wm * 64 + im * 16 + q;
            int col = bn + wn * 32 + in * 8 + 2 * p;
            float b0 = 0.f, b1 = 0.f;
            if (bias) { b0 = bias[col]; b1 = bias[col + 1]; }
            float c0 = acc[im][in][0] + b0;
            float c1 = acc[im][in][1] + b1;
            float c2 = acc[im][in][2] + b0;
            float c3 = acc[im][in][3] + b1;
            if (RELU) {
                c0 = c0 > 0.f ? c0 : 0.f;  c1 = c1 > 0.f ? c1 : 0.f;
                c2 = c2 > 0.f ? c2 : 0.f;  c3 = c3 > 0.f ? c3 : 0.f;
            }
            if (SPLIT) {
                uint32_t hi, lo;
                if (row < M) {
                    split2(c0, c1, hi, lo);
                    *(uint32_t*)&Ch[(size_t)row * Ntot + col] = hi;
                    *(uint32_t*)&Cl[(size_t)row * Ntot + col] = lo;
                }
                if (row + 8 < M) {
                    split2(c2, c3, hi, lo);
                    *(uint32_t*)&Ch[(size_t)(row + 8) * Ntot + col] = hi;
                    *(uint32_t*)&Cl[(size_t)(row + 8) * Ntot + col] = lo;
                }
            } else {
                if (row < M)
                    *(float2*)&Cf[(size_t)row * Ntot + col] = make_float2(c0, c1);
                if (row + 8 < M)
                    *(float2*)&Cf[(size_t)(row + 8) * Ntot + col] = make_float2(c2, c3);
            }
        }
    }
}

// ---------------- conversions ---------------------------------------------
// W: [512, Ncols] fp32 row-major -> T[h|l]: [Ncols, 512] bf16
__global__ void conv_w(const float* __restrict__ W,
                       __nv_bfloat16* __restrict__ Th, __nv_bfloat16* __restrict__ Tl,
                       int Ncols)
{
    int idx = blockIdx.x * blockDim.x + threadIdx.x;
    if (idx >= 512 * Ncols) return;
    int n = idx >> 9, k = idx & 511;
    float v = W[(size_t)k * Ncols + n];
    __nv_bfloat16 h = __float2bfloat16(v);
    Th[idx] = h;
    Tl[idx] = __float2bfloat16(v - __bfloat162float(h));
}

__global__ void conv_x(const float* __restrict__ X,
                       __nv_bfloat16* __restrict__ Xh, __nv_bfloat16* __restrict__ Xl)
{
    size_t idx = (size_t)blockIdx.x * blockDim.x + threadIdx.x;
    if (idx >= (size_t)NN * HH) return;
    float v = X[idx];
    __nv_bfloat16 h = __float2bfloat16(v);
    Xh[idx] = h;
    Xl[idx] = __float2bfloat16(v - __bfloat162float(h));
}

// ---------------- pointwise kernels ---------------------------------------
__device__ __forceinline__ float sigm(float x) { return 1.f / (1.f + expf(-x)); }

__device__ __forceinline__ void wsplit(__nv_bfloat16* Hh, __nv_bfloat16* Hl,
                                       size_t g, float v) {
    __nv_bfloat16 h = __float2bfloat16(v);
    Hh[g] = h;
    Hl[g] = __float2bfloat16(v - __bfloat162float(h));
}

__global__ void hsum_kernel(const __nv_bfloat16* __restrict__ Hh,
                            const __nv_bfloat16* __restrict__ Hl,
                            __nv_bfloat16* __restrict__ Sh,
                            __nv_bfloat16* __restrict__ Sl,
                            int n, int sc)
{
    int idx = blockIdx.x * blockDim.x + threadIdx.x;
    if (idx >= n * HH) return;
    int r = idx >> 9, j = idx & 511;
    size_t base = (size_t)(sc + 4 * r) * HH + j;
    float s = 0.f;
#pragma unroll
    for (int k = 0; k < 4; ++k)
        s += __bfloat162float(Hh[base + k * HH]) + __bfloat162float(Hl[base + k * HH]);
    wsplit(Sh, Sl, idx, s);
}

__global__ void leaf_pw(const float* __restrict__ iou,
                        const float* __restrict__ bix, const float* __restrict__ bih,
                        __nv_bfloat16* __restrict__ Hh, __nv_bfloat16* __restrict__ Hl,
                        float* __restrict__ cell)
{
    int idx = blockIdx.x * blockDim.x + threadIdx.x;
    if (idx >= NLEAF * HH) return;
    int r = idx >> 9, j = idx & 511;
    const float* row = iou + (size_t)r * 1536;
    float i = sigm (row[j]        + bix[j]        + bih[j]);
    float o = sigm (row[512 + j]  + bix[512 + j]  + bih[512 + j]);
    float u = tanhf(row[1024 + j] + bix[1024 + j] + bih[1024 + j]);
    float c = i * u;
    size_t g = (size_t)(SLEAF + r) * HH + j;
    cell[g] = c;
    wsplit(Hh, Hl, g, o * tanhf(c));
}

__global__ void int_pw(const float* __restrict__ iou, const float* __restrict__ fx,
                       const float* __restrict__ fh,
                       const float* __restrict__ bix, const float* __restrict__ bih,
                       const float* __restrict__ bfx, const float* __restrict__ bfh,
                       __nv_bfloat16* __restrict__ Hh, __nv_bfloat16* __restrict__ Hl,
                       float* __restrict__ cell,
                       int n, int s, int sc)
{
    int idx = blockIdx.x * blockDim.x + threadIdx.x;
    if (idx >= n * HH) return;
    int r = idx >> 9, j = idx & 511;
    const float* row = iou + (size_t)r * 1536;
    float i = sigm (row[j]        + bix[j]        + bih[j]);
    float o = sigm (row[512 + j]  + bix[512 + j]  + bih[512 + j]);
    float u = tanhf(row[1024 + j] + bix[1024 + j] + bih[1024 + j]);
    float fxv = fx[(size_t)r * HH + j] + bfx[j] + bfh[j];
    float acc = i * u;
#pragma unroll
    for (int k = 0; k < 4; ++k) {
        float f = sigm(fxv + fh[(size_t)(4 * r + k) * HH + j]);
        acc += f * cell[(size_t)(sc + 4 * r + k) * HH + j];
    }
    size_t g = (size_t)(s + r) * HH + j;
    cell[g] = acc;
    wsplit(Hh, Hl, g, o * tanhf(acc));
}

__global__ void colsum_part(const __nv_bfloat16* __restrict__ Hh,
                            const __nv_bfloat16* __restrict__ Hl,
                            float* __restrict__ part)
{
    int b = blockIdx.x;
    const int rows_per = (NN + 511) / 512;
    int r0 = b * rows_per;
    int r1 = r0 + rows_per; if (r1 > NN) r1 = NN;
    for (int j = threadIdx.x; j < HH; j += blockDim.x) {
        float s = 0.f;
        for (int r = r0; r < r1; ++r) {
            size_t g = (size_t)r * HH + j;
            s += __bfloat162float(Hh[g]) + __bfloat162float(Hl[g]);
        }
        part[(size_t)b * HH + j] = s;
    }
}

__global__ void colsum_final(const float* __restrict__ part, float* __restrict__ cs)
{
    int j = blockIdx.x * blockDim.x + threadIdx.x;
    if (j >= HH) return;
    float acc = 0.f;
    for (int b = 0; b < 512; ++b) acc += part[(size_t)b * HH + j];
    cs[j] = acc;
}

__global__ void tree_kernel(const float* __restrict__ cs, const float* __restrict__ W_out,
                            const float* __restrict__ b_out, float* __restrict__ out)
{
    int j = threadIdx.x;
    float acc = (float)NN * b_out[j];
    for (int k = 0; k < HH; ++k) acc += cs[k] * W_out[(size_t)k * OUTF + j];
    out[j] = acc;
}

// ---------------- driver ---------------------------------------------------
static void* symv(const void* s) { void* p = nullptr; cudaGetSymbolAddress(&p, s); return p; }

extern "C" void kernel_launch(void* const* d_in, const int* in_sizes, int n_in,
                              void* d_out, int out_size)
{
    (void)in_sizes; (void)n_in; (void)out_size;
    const float* x      = (const float*)d_in[0];
    const float* W_in   = (const float*)d_in[8];
    const float* b_in   = (const float*)d_in[9];
    const float* W_ioux = (const float*)d_in[10];
    const float* b_ioux = (const float*)d_in[11];
    const float* W_iouh = (const float*)d_in[12];
    const float* b_iouh = (const float*)d_in[13];
    const float* W_fx   = (const float*)d_in[14];
    const float* b_fx   = (const float*)d_in[15];
    const float* W_fh   = (const float*)d_in[16];
    const float* b_fh   = (const float*)d_in[17];
    const float* W_out  = (const float*)d_in[18];
    const float* b_out  = (const float*)d_in[19];
    float* out = (float*)d_out;

    __nv_bfloat16* wh  = (__nv_bfloat16*)symv(g_wh);
    __nv_bfloat16* wl  = (__nv_bfloat16*)symv(g_wl);
    __nv_bfloat16* xh  = (__nv_bfloat16*)symv(g_xh);
    __nv_bfloat16* xl  = (__nv_bfloat16*)symv(g_xl);
    __nv_bfloat16* h0h = (__nv_bfloat16*)symv(g_h0h);
    __nv_bfloat16* h0l = (__nv_bfloat16*)symv(g_h0l);
    __nv_bfloat16* hih = (__nv_bfloat16*)symv(g_hih);
    __nv_bfloat16* hil = (__nv_bfloat16*)symv(g_hil);
    __nv_bfloat16* hsh = (__nv_bfloat16*)symv(g_hsh);
    __nv_bfloat16* hsl = (__nv_bfloat16*)symv(g_hsl);
    float* cell = (float*)symv(g_cell);
    float* iou  = (float*)symv(g_iou);
    float* fx   = (float*)symv(g_fx);
    float* fh   = (float*)symv(g_fh);
    float* part = (float*)symv(g_part);
    float* cs   = (float*)symv(g_cs);

    const int SMB = 4 * STGE * 2;  // 98304 B (4 stages)
    cudaFuncSetAttribute(gemm_mma<false,false>, cudaFuncAttributeMaxDynamicSharedMemorySize, SMB);
    cudaFuncSetAttribute(gemm_mma<true,true>,   cudaFuncAttributeMaxDynamicSharedMemorySize, SMB);

    // ---- conversions
    conv_w<<<(512 * 512 + 255) / 256, 256>>>(W_in, wh + OFF_WIN, wl + OFF_WIN, 512);
    conv_w<<<(512 * 1536 + 255) / 256, 256>>>(W_ioux,              wh + OFF_IOUX0, wl + OFF_IOUX0, 1536);
    conv_w<<<(512 * 1536 + 255) / 256, 256>>>(W_ioux + 512 * 1536, wh + OFF_IOUX1, wl + OFF_IOUX1, 1536);
    conv_w<<<(512 * 1536 + 255) / 256, 256>>>(W_iouh,              wh + OFF_IOUH0, wl + OFF_IOUH0, 1536);
    conv_w<<<(512 * 1536 + 255) / 256, 256>>>(W_iouh + 512 * 1536, wh + OFF_IOUH1, wl + OFF_IOUH1, 1536);
    conv_w<<<(512 * 512 + 255) / 256, 256>>>(W_fx,             wh + OFF_FX0, wl + OFF_FX0, 512);
    conv_w<<<(512 * 512 + 255) / 256, 256>>>(W_fx + 512 * 512, wh + OFF_FX1, wl + OFF_FX1, 512);
    conv_w<<<(512 * 512 + 255) / 256, 256>>>(W_fh,             wh + OFF_FH0, wl + OFF_FH0, 512);
    conv_w<<<(512 * 512 + 255) / 256, 256>>>(W_fh + 512 * 512, wh + OFF_FH1, wl + OFF_FH1, 512);
    conv_w<<<(512 * 256 + 255) / 256, 256>>>(W_out, wh + OFF_WOUT, wl + OFF_WOUT, 256);
    conv_x<<<(int)(((size_t)NN * HH + 255) / 256), 256>>>(x, xh, xl);

    const int MT_ALL = (NN + 127) / 128;   // 683

    // ---- input projection: h0 = relu(x @ W_in + b_in), split output
    gemm_mma<true,true><<<dim3(4, MT_ALL), 256, SMB>>>(
        xh, xl, wh + OFF_WIN, wl + OFF_WIN,
        nullptr, nullptr, nullptr, nullptr,
        b_in, nullptr, h0h, h0l, NN, HH);

    const int offX[2] = {OFF_IOUX0, OFF_IOUX1};
    const int offH[2] = {OFF_IOUH0, OFF_IOUH1};
    const int offF[2] = {OFF_FX0, OFF_FX1};
    const int offG[2] = {OFF_FH0, OFF_FH1};

    for (int l = 0; l < 2; ++l) {
        __nv_bfloat16* hinh = (l == 0) ? h0h : hih;
        __nv_bfloat16* hinl = (l == 0) ? h0l : hil;
        __nv_bfloat16* houth = (l == 0) ? hih : h0h;
        __nv_bfloat16* houtl = (l == 0) ? hil : h0l;
        const float* Bix = b_ioux + (size_t)l * 1536;
        const float* Bih = b_iouh + (size_t)l * 1536;
        const float* Bfx = b_fx   + (size_t)l * HH;
        const float* Bfh = b_fh   + (size_t)l * HH;

        // leaf level
        gemm_mma<false,false><<<dim3(12, NLEAF / 128), 256, SMB>>>(
            hinh + (size_t)SLEAF * HH, hinl + (size_t)SLEAF * HH,
            wh + offX[l], wl + offX[l],
            nullptr, nullptr, nullptr, nullptr,
            nullptr, iou, nullptr, nullptr, NLEAF, 1536);
        leaf_pw<<<(NLEAF * HH) / 256, 256>>>(iou, Bix, Bih, houth, houtl, cell);

        for (int d = 7; d >= 0; --d) {
            int s  = LS[d];
            int n  = LS[d + 1] - LS[d];
            int sc = LS[d + 1];
            int mt  = (n + 127) / 128;
            int mt4 = (4 * n + 127) / 128;
            int nblk_pw = (n * HH + 255) / 256;

            hsum_kernel<<<nblk_pw, 256>>>(houth, houtl, hsh, hsl, n, sc);
            gemm_mma<false,false><<<dim3(12, mt), 256, SMB>>>(
                hinh + (size_t)s * HH, hinl + (size_t)s * HH,
                wh + offX[l], wl + offX[l],
                hsh, hsl, wh + offH[l], wl + offH[l],
                nullptr, iou, nullptr, nullptr, n, 1536);
            gemm_mma<false,false><<<dim3(4, mt), 256, SMB>>>(
                hinh + (size_t)s * HH, hinl + (size_t)s * HH,
                wh + offF[l], wl + offF[l],
                nullptr, nullptr, nullptr, nullptr,
                nullptr, fx, nullptr, nullptr, n, HH);
            gemm_mma<false,false><<<dim3(4, mt4), 256, SMB>>>(
                houth + (size_t)sc * HH, houtl + (size_t)sc * HH,
                wh + offG[l], wl + offG[l],
                nullptr, nullptr, nullptr, nullptr,
                nullptr, fh, nullptr, nullptr, 4 * n, HH);
            int_pw<<<nblk_pw, 256>>>(iou, fx, fh, Bix, Bih, Bfx, Bfh,
                                     houth, houtl, cell, n, s, sc);
        }
    }

    // node_emb = h0 @ W_out + b_out
    gemm_mma<false,false><<<dim3(2, MT_ALL), 256, SMB>>>(
        h0h, h0l, wh + OFF_WOUT, wl + OFF_WOUT,
        nullptr, nullptr, nullptr, nullptr,
        b_out, out, nullptr, nullptr, NN, OUTF);

    // tree_emb
    colsum_part<<<512, 256>>>(h0h, h0l, part);
    colsum_final<<<2, 256>>>(part, cs);
    tree_kernel<<<1, 256>>>(cs, W_out, b_out, out + (size_t)NN * OUTF);
}

// round 7
// speedup vs baseline: 1.1530x; 1.1530x over previous
#include <cuda_runtime.h>
#include <cuda_bf16.h>
#include <cstdint>
#include <math.h>

// ---------------- problem constants ----------------
#define NN     87381
#define HH     512
#define OUTF   256
#define NLEAF  65536
#define SLEAF  21845
static const int LS[10] = {0,1,5,21,85,341,1365,5461,21845,87381};

// converted weight offsets (elements), all [N,K=512] row-major bf16
// CX_l = [W_ioux_l (1536 rows) | W_fx_l (512 rows)]  (2048 x 512)
// CH_l = [W_iouh_l (1536 rows) | zeros  (512 rows)]  (2048 x 512)
#define OFF_WIN    0
#define OFF_CX0    262144
#define OFF_CX1    1310720
#define OFF_CH0    2359296
#define OFF_CH1    3407872
#define OFF_FH0    4456448
#define OFF_FH1    4718592
#define OFF_WOUT   4980736
#define WTOT       5111808
#define FXROW      786432     // 1536*512: offset of FX part within CX

// ---------------- scratch (device globals; no allocation) ----------
__device__ __nv_bfloat16 g_wh[WTOT];
__device__ __nv_bfloat16 g_wl[WTOT];
__device__ __nv_bfloat16 g_xh [(size_t)NN * HH];
__device__ __nv_bfloat16 g_xl [(size_t)NN * HH];
__device__ __nv_bfloat16 g_h0h[(size_t)NN * HH];
__device__ __nv_bfloat16 g_h0l[(size_t)NN * HH];
__device__ __nv_bfloat16 g_hih[(size_t)NN * HH];
__device__ __nv_bfloat16 g_hil[(size_t)NN * HH];
__device__ __nv_bfloat16 g_hsh[(size_t)16384 * HH];
__device__ __nv_bfloat16 g_hsl[(size_t)16384 * HH];
__device__ float g_cell[(size_t)NN * HH];
__device__ float g_iou [(size_t)NLEAF * 1536];    // also holds [n,2048] internal
__device__ float g_fh  [(size_t)NLEAF * HH];
__device__ float g_part[(size_t)512 * HH];
__device__ float g_cs  [HH];

// ---------------- portable PTX helpers (sm_80+ only) ----------------
__device__ __forceinline__ void mma16816(float* c, const uint32_t* a, const uint32_t* b) {
    asm volatile(
        "mma.sync.aligned.m16n8k16.row.col.f32.bf16.bf16.f32 "
        "{%0,%1,%2,%3}, {%4,%5,%6,%7}, {%8,%9}, {%0,%1,%2,%3};"
        : "+f"(c[0]), "+f"(c[1]), "+f"(c[2]), "+f"(c[3])
        : "r"(a[0]), "r"(a[1]), "r"(a[2]), "r"(a[3]), "r"(b[0]), "r"(b[1]));
}
__device__ __forceinline__ void cp16z(uint16_t* dst, const void* src, bool pred) {
    uint32_t d = (uint32_t)__cvta_generic_to_shared(dst);
    int sz = pred ? 16 : 0;
    asm volatile("cp.async.cg.shared.global [%0], [%1], 16, %2;" :: "r"(d), "l"(src), "r"(sz));
}
__device__ __forceinline__ void cp_commit() { asm volatile("cp.async.commit_group;" ::: "memory"); }
__device__ __forceinline__ void cp_wait2()  { asm volatile("cp.async.wait_group 2;"  ::: "memory"); }

__device__ __forceinline__ void split2(float a, float b, uint32_t& hi, uint32_t& lo) {
    __nv_bfloat16 h0 = __float2bfloat16(a), h1 = __float2bfloat16(b);
    __nv_bfloat16 l0 = __float2bfloat16(a - __bfloat162float(h0));
    __nv_bfloat16 l1 = __float2bfloat16(b - __bfloat162float(h1));
    hi = (uint32_t)*(uint16_t*)&h0 | ((uint32_t)*(uint16_t*)&h1 << 16);
    lo = (uint32_t)*(uint16_t*)&l0 | ((uint32_t)*(uint16_t*)&l1 << 16);
}

// ---------------- mma.sync GEMM ------------------------------------------
// C = [A1@B1^T (+ A2@B2^T)] (+bias)(+relu). All operands bf16 hi/lo pairs.
// K = 512 per pass. CTA tile 128x128, 8 warps (2m x 4n), warp tile 64x32,
// K chunk 16. 4-stage cp.async pipeline, ONE barrier per chunk.
// 3-pass split with pass-separated MMA order (RAW distance 4, not 1).
#define ASTR 24
#define TE   3072       // 128*24 elems per tile
#define STGE 12288      // 4 tiles per stage (24576 B)

template <bool RELU, bool SPLIT>
__global__ __launch_bounds__(256, 2) void gemm_mma(
    const __nv_bfloat16* __restrict__ A1h, const __nv_bfloat16* __restrict__ A1l,
    const __nv_bfloat16* __restrict__ B1h, const __nv_bfloat16* __restrict__ B1l,
    const __nv_bfloat16* __restrict__ A2h, const __nv_bfloat16* __restrict__ A2l,
    const __nv_bfloat16* __restrict__ B2h, const __nv_bfloat16* __restrict__ B2l,
    const float* __restrict__ bias,
    float* __restrict__ Cf,
    __nv_bfloat16* __restrict__ Ch, __nv_bfloat16* __restrict__ Cl,
    int M, int Ntot)
{
    extern __shared__ uint16_t sm16[];
    const int t    = threadIdx.x;
    const int lane = t & 31, wid = t >> 5;
    const int q = lane >> 2, p = lane & 3;
    const int wm = wid >> 2, wn = wid & 3;       // 2 x 4 warps, tile 64x32
    const int bm = blockIdx.y * 128;
    const int bn = blockIdx.x * 128;

    const int r  = t >> 1;          // staging row 0..127
    const int hf = t & 1;           // 8-elem half

    const int npass = (A2h != nullptr) ? 2 : 1;
    const int CT = npass * 32;

    float acc[4][4][4];
#pragma unroll
    for (int im = 0; im < 4; ++im)
#pragma unroll
        for (int in = 0; in < 4; ++in)
#pragma unroll
            for (int k = 0; k < 4; ++k) acc[im][in][k] = 0.f;

    auto stage = [&](int cc) {
        const int pass = cc >> 5, k0 = (cc & 31) * 16;
        const __nv_bfloat16* Ah = pass ? A2h : A1h;
        const __nv_bfloat16* Al = pass ? A2l : A1l;
        const __nv_bfloat16* Bh = pass ? B2h : B1h;
        const __nv_bfloat16* Bl = pass ? B2l : B1l;
        uint16_t* stg = sm16 + (cc & 3) * STGE;
        const bool pa = (bm + r < M);
        const size_t asrc = (size_t)(bm + r) * 512 + k0 + hf * 8;
        const size_t bsrc = (size_t)(bn + r) * 512 + k0 + hf * 8;
        uint16_t* dst = stg + r * ASTR + hf * 8;
        cp16z(dst,          Ah + asrc, pa);
        cp16z(dst + TE,     Al + asrc, pa);
        cp16z(dst + 2 * TE, Bh + bsrc, true);
        cp16z(dst + 3 * TE, Bl + bsrc, true);
    };

    stage(0); cp_commit();
    if (CT > 1) { stage(1); cp_commit(); }

    for (int c = 0; c < CT; ++c) {
        if (c + 2 < CT) stage(c + 2);
        cp_commit();
        cp_wait2();
        __syncthreads();

        const uint16_t* stg = sm16 + (c & 3) * STGE;
        const uint16_t* AH = stg;
        const uint16_t* AL = stg + TE;
        const uint16_t* BH = stg + 2 * TE;
        const uint16_t* BL = stg + 3 * TE;

        uint32_t bh[4][2], bl[4][2];
#pragma unroll
        for (int in = 0; in < 4; ++in) {
            int off = (wn * 32 + in * 8 + q) * ASTR + 2 * p;
            bh[in][0] = *(const uint32_t*)(BH + off);
            bh[in][1] = *(const uint32_t*)(BH + off + 8);
            bl[in][0] = *(const uint32_t*)(BL + off);
            bl[in][1] = *(const uint32_t*)(BL + off + 8);
        }
#pragma unroll
        for (int im = 0; im < 4; ++im) {
            int off = (wm * 64 + im * 16 + q) * ASTR + 2 * p;
            uint32_t ah[4], al[4];
            ah[0] = *(const uint32_t*)(AH + off);
            ah[1] = *(const uint32_t*)(AH + off + 8 * ASTR);
            ah[2] = *(const uint32_t*)(AH + off + 8);
            ah[3] = *(const uint32_t*)(AH + off + 8 * ASTR + 8);
            al[0] = *(const uint32_t*)(AL + off);
            al[1] = *(const uint32_t*)(AL + off + 8 * ASTR);
            al[2] = *(const uint32_t*)(AL + off + 8);
            al[3] = *(const uint32_t*)(AL + off + 8 * ASTR + 8);
            // pass-separated: same-acc RAW distance = 4 MMAs, not 1
#pragma unroll
            for (int in = 0; in < 4; ++in) mma16816(acc[im][in], ah, bh[in]);
#pragma unroll
            for (int in = 0; in < 4; ++in) mma16816(acc[im][in], ah, bl[in]);
#pragma unroll
            for (int in = 0; in < 4; ++in) mma16816(acc[im][in], al, bh[in]);
        }
    }

    // ---- epilogue
#pragma unroll
    for (int im = 0; im < 4; ++im) {
#pragma unroll
        for (int in = 0; in < 4; ++in) {
            int row = bm + wm * 64 + im * 16 + q;
            int col = bn + wn * 32 + in * 8 + 2 * p;
            float b0 = 0.f, b1 = 0.f;
            if (bias) { b0 = bias[col]; b1 = bias[col + 1]; }
            float c0 = acc[im][in][0] + b0;
            float c1 = acc[im][in][1] + b1;
            float c2 = acc[im][in][2] + b0;
            float c3 = acc[im][in][3] + b1;
            if (RELU) {
                c0 = c0 > 0.f ? c0 : 0.f;  c1 = c1 > 0.f ? c1 : 0.f;
                c2 = c2 > 0.f ? c2 : 0.f;  c3 = c3 > 0.f ? c3 : 0.f;
            }
            if (SPLIT) {
                uint32_t hi, lo;
                if (row < M) {
                    split2(c0, c1, hi, lo);
                    *(uint32_t*)&Ch[(size_t)row * Ntot + col] = hi;
                    *(uint32_t*)&Cl[(size_t)row * Ntot + col] = lo;
                }
                if (row + 8 < M) {
                    split2(c2, c3, hi, lo);
                    *(uint32_t*)&Ch[(size_t)(row + 8) * Ntot + col] = hi;
                    *(uint32_t*)&Cl[(size_t)(row + 8) * Ntot + col] = lo;
                }
            } else {
                if (row < M)
                    *(float2*)&Cf[(size_t)row * Ntot + col] = make_float2(c0, c1);
                if (row + 8 < M)
                    *(float2*)&Cf[(size_t)(row + 8) * Ntot + col] = make_float2(c2, c3);
            }
        }
    }
}

// ---------------- conversions ---------------------------------------------
// W: [512, Ncols] fp32 row-major -> T[h|l]: [Ncols, 512] bf16
__global__ void conv_w(const float* __restrict__ W,
                       __nv_bfloat16* __restrict__ Th, __nv_bfloat16* __restrict__ Tl,
                       int Ncols)
{
    int idx = blockIdx.x * blockDim.x + threadIdx.x;
    if (idx >= 512 * Ncols) return;
    int n = idx >> 9, k = idx & 511;
    float v = W[(size_t)k * Ncols + n];
    __nv_bfloat16 h = __float2bfloat16(v);
    Th[idx] = h;
    Tl[idx] = __float2bfloat16(v - __bfloat162float(h));
}

__global__ void conv_x(const float* __restrict__ X,
                       __nv_bfloat16* __restrict__ Xh, __nv_bfloat16* __restrict__ Xl)
{
    size_t idx = (size_t)blockIdx.x * blockDim.x + threadIdx.x;
    if (idx >= (size_t)NN * HH) return;
    float v = X[idx];
    __nv_bfloat16 h = __float2bfloat16(v);
    Xh[idx] = h;
    Xl[idx] = __float2bfloat16(v - __bfloat162float(h));
}

// ---------------- pointwise kernels ---------------------------------------
__device__ __forceinline__ float sigm(float x) { return 1.f / (1.f + expf(-x)); }

__device__ __forceinline__ void wsplit(__nv_bfloat16* Hh, __nv_bfloat16* Hl,
                                       size_t g, float v) {
    __nv_bfloat16 h = __float2bfloat16(v);
    Hh[g] = h;
    Hl[g] = __float2bfloat16(v - __bfloat162float(h));
}

__global__ void hsum_kernel(const __nv_bfloat16* __restrict__ Hh,
                            const __nv_bfloat16* __restrict__ Hl,
                            __nv_bfloat16* __restrict__ Sh,
                            __nv_bfloat16* __restrict__ Sl,
                            int n, int sc)
{
    int idx = blockIdx.x * blockDim.x + threadIdx.x;
    if (idx >= n * HH) return;
    int r = idx >> 9, j = idx & 511;
    size_t base = (size_t)(sc + 4 * r) * HH + j;
    float s = 0.f;
#pragma unroll
    for (int k = 0; k < 4; ++k)
        s += __bfloat162float(Hh[base + k * HH]) + __bfloat162float(Hl[base + k * HH]);
    wsplit(Sh, Sl, idx, s);
}

__global__ void leaf_pw(const float* __restrict__ iou,
                        const float* __restrict__ bix, const float* __restrict__ bih,
                        __nv_bfloat16* __restrict__ Hh, __nv_bfloat16* __restrict__ Hl,
                        float* __restrict__ cell)
{
    int idx = blockIdx.x * blockDim.x + threadIdx.x;
    if (idx >= NLEAF * HH) return;
    int r = idx >> 9, j = idx & 511;
    const float* row = iou + (size_t)r * 1536;
    float i = sigm (row[j]        + bix[j]        + bih[j]);
    float o = sigm (row[512 + j]  + bix[512 + j]  + bih[512 + j]);
    float u = tanhf(row[1024 + j] + bix[1024 + j] + bih[1024 + j]);
    float c = i * u;
    size_t g = (size_t)(SLEAF + r) * HH + j;
    cell[g] = c;
    wsplit(Hh, Hl, g, o * tanhf(c));
}

// combined buffer row layout: [i(512) | o(512) | u(512) | fx(512)], stride 2048
__global__ void int_pw(const float* __restrict__ cio, const float* __restrict__ fh,
                       const float* __restrict__ bix, const float* __restrict__ bih,
                       const float* __restrict__ bfx, const float* __restrict__ bfh,
                       __nv_bfloat16* __restrict__ Hh, __nv_bfloat16* __restrict__ Hl,
                       float* __restrict__ cell,
                       int n, int s, int sc)
{
    int idx = blockIdx.x * blockDim.x + threadIdx.x;
    if (idx >= n * HH) return;
    int r = idx >> 9, j = idx & 511;
    const float* row = cio + (size_t)r * 2048;
    float i = sigm (row[j]        + bix[j]        + bih[j]);
    float o = sigm (row[512 + j]  + bix[512 + j]  + bih[512 + j]);
    float u = tanhf(row[1024 + j] + bix[1024 + j] + bih[1024 + j]);
    float fxv = row[1536 + j] + bfx[j] + bfh[j];
    float acc = i * u;
#pragma unroll
    for (int k = 0; k < 4; ++k) {
        float f = sigm(fxv + fh[(size_t)(4 * r + k) * HH + j]);
        acc += f * cell[(size_t)(sc + 4 * r + k) * HH + j];
    }
    size_t g = (size_t)(s + r) * HH + j;
    cell[g] = acc;
    wsplit(Hh, Hl, g, o * tanhf(acc));
}

__global__ void colsum_part(const __nv_bfloat16* __restrict__ Hh,
                            const __nv_bfloat16* __restrict__ Hl,
                            float* __restrict__ part)
{
    int b = blockIdx.x;
    const int rows_per = (NN + 511) / 512;
    int r0 = b * rows_per;
    int r1 = r0 + rows_per; if (r1 > NN) r1 = NN;
    for (int j = threadIdx.x; j < HH; j += blockDim.x) {
        float s = 0.f;
        for (int r = r0; r < r1; ++r) {
            size_t g = (size_t)r * HH + j;
            s += __bfloat162float(Hh[g]) + __bfloat162float(Hl[g]);
        }
        part[(size_t)b * HH + j] = s;
    }
}

__global__ void colsum_final(const float* __restrict__ part, float* __restrict__ cs)
{
    int j = blockIdx.x * blockDim.x + threadIdx.x;
    if (j >= HH) return;
    float acc = 0.f;
    for (int b = 0; b < 512; ++b) acc += part[(size_t)b * HH + j];
    cs[j] = acc;
}

__global__ void tree_kernel(const float* __restrict__ cs, const float* __restrict__ W_out,
                            const float* __restrict__ b_out, float* __restrict__ out)
{
    int j = threadIdx.x;
    float acc = (float)NN * b_out[j];
    for (int k = 0; k < HH; ++k) acc += cs[k] * W_out[(size_t)k * OUTF + j];
    out[j] = acc;
}

// ---------------- driver ---------------------------------------------------
static void* symv(const void* s) { void* p = nullptr; cudaGetSymbolAddress(&p, s); return p; }

extern "C" void kernel_launch(void* const* d_in, const int* in_sizes, int n_in,
                              void* d_out, int out_size)
{
    (void)in_sizes; (void)n_in; (void)out_size;
    const float* x      = (const float*)d_in[0];
    const float* W_in   = (const float*)d_in[8];
    const float* b_in   = (const float*)d_in[9];
    const float* W_ioux = (const float*)d_in[10];
    const float* b_ioux = (const float*)d_in[11];
    const float* W_iouh = (const float*)d_in[12];
    const float* b_iouh = (const float*)d_in[13];
    const float* W_fx   = (const float*)d_in[14];
    const float* b_fx   = (const float*)d_in[15];
    const float* W_fh   = (const float*)d_in[16];
    const float* b_fh   = (const float*)d_in[17];
    const float* W_out  = (const float*)d_in[18];
    const float* b_out  = (const float*)d_in[19];
    float* out = (float*)d_out;

    __nv_bfloat16* wh  = (__nv_bfloat16*)symv(g_wh);
    __nv_bfloat16* wl  = (__nv_bfloat16*)symv(g_wl);
    __nv_bfloat16* xh  = (__nv_bfloat16*)symv(g_xh);
    __nv_bfloat16* xl  = (__nv_bfloat16*)symv(g_xl);
    __nv_bfloat16* h0h = (__nv_bfloat16*)symv(g_h0h);
    __nv_bfloat16* h0l = (__nv_bfloat16*)symv(g_h0l);
    __nv_bfloat16* hih = (__nv_bfloat16*)symv(g_hih);
    __nv_bfloat16* hil = (__nv_bfloat16*)symv(g_hil);
    __nv_bfloat16* hsh = (__nv_bfloat16*)symv(g_hsh);
    __nv_bfloat16* hsl = (__nv_bfloat16*)symv(g_hsl);
    float* cell = (float*)symv(g_cell);
    float* iou  = (float*)symv(g_iou);
    float* fh   = (float*)symv(g_fh);
    float* part = (float*)symv(g_part);
    float* cs   = (float*)symv(g_cs);

    const int SMB = 4 * STGE * 2;  // 98304 B (4 stages)
    cudaFuncSetAttribute(gemm_mma<false,false>, cudaFuncAttributeMaxDynamicSharedMemorySize, SMB);
    cudaFuncSetAttribute(gemm_mma<true,true>,   cudaFuncAttributeMaxDynamicSharedMemorySize, SMB);

    // ---- conversions (transpose + bf16 hi/lo split)
    conv_w<<<(512 * 512 + 255) / 256, 256>>>(W_in, wh + OFF_WIN, wl + OFF_WIN, 512);
    conv_w<<<(512 * 1536 + 255) / 256, 256>>>(W_ioux,              wh + OFF_CX0, wl + OFF_CX0, 1536);
    conv_w<<<(512 * 1536 + 255) / 256, 256>>>(W_ioux + 512 * 1536, wh + OFF_CX1, wl + OFF_CX1, 1536);
    conv_w<<<(512 * 512 + 255) / 256, 256>>>(W_fx,             wh + OFF_CX0 + FXROW, wl + OFF_CX0 + FXROW, 512);
    conv_w<<<(512 * 512 + 255) / 256, 256>>>(W_fx + 512 * 512, wh + OFF_CX1 + FXROW, wl + OFF_CX1 + FXROW, 512);
    conv_w<<<(512 * 1536 + 255) / 256, 256>>>(W_iouh,              wh + OFF_CH0, wl + OFF_CH0, 1536);
    conv_w<<<(512 * 1536 + 255) / 256, 256>>>(W_iouh + 512 * 1536, wh + OFF_CH1, wl + OFF_CH1, 1536);
    cudaMemsetAsync(wh + OFF_CH0 + FXROW, 0, 512 * 512 * 2);
    cudaMemsetAsync(wl + OFF_CH0 + FXROW, 0, 512 * 512 * 2);
    cudaMemsetAsync(wh + OFF_CH1 + FXROW, 0, 512 * 512 * 2);
    cudaMemsetAsync(wl + OFF_CH1 + FXROW, 0, 512 * 512 * 2);
    conv_w<<<(512 * 512 + 255) / 256, 256>>>(W_fh,             wh + OFF_FH0, wl + OFF_FH0, 512);
    conv_w<<<(512 * 512 + 255) / 256, 256>>>(W_fh + 512 * 512, wh + OFF_FH1, wl + OFF_FH1, 512);
    conv_w<<<(512 * 256 + 255) / 256, 256>>>(W_out, wh + OFF_WOUT, wl + OFF_WOUT, 256);
    conv_x<<<(int)(((size_t)NN * HH + 255) / 256), 256>>>(x, xh, xl);

    const int MT_ALL = (NN + 127) / 128;   // 683

    // ---- input projection: h0 = relu(x @ W_in + b_in), split output
    gemm_mma<true,true><<<dim3(4, MT_ALL), 256, SMB>>>(
        xh, xl, wh + OFF_WIN, wl + OFF_WIN,
        nullptr, nullptr, nullptr, nullptr,
        b_in, nullptr, h0h, h0l, NN, HH);

    const int offCX[2] = {OFF_CX0, OFF_CX1};
    const int offCH[2] = {OFF_CH0, OFF_CH1};
    const int offFH[2] = {OFF_FH0, OFF_FH1};

    for (int l = 0; l < 2; ++l) {
        __nv_bfloat16* hinh = (l == 0) ? h0h : hih;
        __nv_bfloat16* hinl = (l == 0) ? h0l : hil;
        __nv_bfloat16* houth = (l == 0) ? hih : h0h;
        __nv_bfloat16* houtl = (l == 0) ? hil : h0l;
        const float* Bix = b_ioux + (size_t)l * 1536;
        const float* Bih = b_iouh + (size_t)l * 1536;
        const float* Bfx = b_fx   + (size_t)l * HH;
        const float* Bfh = b_fh   + (size_t)l * HH;

        // leaf level: iou only (rows 0..1535 of CX = W_ioux), stride 1536
        gemm_mma<false,false><<<dim3(12, NLEAF / 128), 256, SMB>>>(
            hinh + (size_t)SLEAF * HH, hinl + (size_t)SLEAF * HH,
            wh + offCX[l], wl + offCX[l],
            nullptr, nullptr, nullptr, nullptr,
            nullptr, iou, nullptr, nullptr, NLEAF, 1536);
        leaf_pw<<<(NLEAF * HH) / 256, 256>>>(iou, Bix, Bih, houth, houtl, cell);

        for (int d = 7; d >= 0; --d) {
            int s  = LS[d];
            int n  = LS[d + 1] - LS[d];
            int sc = LS[d + 1];
            int mt  = (n + 127) / 128;
            int mt4 = (4 * n + 127) / 128;
            int nblk_pw = (n * HH + 255) / 256;

            hsum_kernel<<<nblk_pw, 256>>>(houth, houtl, hsh, hsl, n, sc);
            // combined iou + fx: C[n, 2048] = hin@[Wix|Wfx] + hsum@[Wih|0]
            gemm_mma<false,false><<<dim3(16, mt), 256, SMB>>>(
                hinh + (size_t)s * HH, hinl + (size_t)s * HH,
                wh + offCX[l], wl + offCX[l],
                hsh, hsl, wh + offCH[l], wl + offCH[l],
                nullptr, iou, nullptr, nullptr, n, 2048);
            gemm_mma<false,false><<<dim3(4, mt4), 256, SMB>>>(
                houth + (size_t)sc * HH, houtl + (size_t)sc * HH,
                wh + offFH[l], wl + offFH[l],
                nullptr, nullptr, nullptr, nullptr,
                nullptr, fh, nullptr, nullptr, 4 * n, HH);
            int_pw<<<nblk_pw, 256>>>(iou, fh, Bix, Bih, Bfx, Bfh,
                                     houth, houtl, cell, n, s, sc);
        }
    }

    // node_emb = h0 @ W_out + b_out
    gemm_mma<false,false><<<dim3(2, MT_ALL), 256, SMB>>>(
        h0h, h0l, wh + OFF_WOUT, wl + OFF_WOUT,
        nullptr, nullptr, nullptr, nullptr,
        b_out, out, nullptr, nullptr, NN, OUTF);

    // tree_emb
    colsum_part<<<512, 256>>>(h0h, h0l, part);
    colsum_final<<<2, 256>>>(part, cs);
    tree_kernel<<<1, 256>>>(cs, W_out, b_out, out + (size_t)NN * OUTF);
}

// round 8
// speedup vs baseline: 1.5097x; 1.3094x over previous
#include <cuda_runtime.h>
#include <cuda_bf16.h>
#include <cuda_fp16.h>
#include <cstdint>
#include <math.h>

// ---------------- problem constants ----------------
#define NN     87381
#define HH     512
#define OUTF   256
#define NLEAF  65536
#define SLEAF  21845
static const int LS[10] = {0,1,5,21,85,341,1365,5461,21845,87381};

// converted weight offsets (elements), all [N,K=512] row-major
// hi limb fp16, lo limb bf16 (residual)
// CX_l = [W_ioux_l (1536 rows) | W_fx_l (512 rows)]  (2048 x 512)
// CH_l = [W_iouh_l (1536 rows) | zeros  (512 rows)]  (2048 x 512)
#define OFF_WIN    0
#define OFF_CX0    262144
#define OFF_CX1    1310720
#define OFF_CH0    2359296
#define OFF_CH1    3407872
#define OFF_FH0    4456448
#define OFF_FH1    4718592
#define OFF_WOUT   4980736
#define WTOT       5111808
#define FXROW      786432     // 1536*512: offset of FX part within CX

// ---------------- scratch (device globals; no allocation) ----------
__device__ __half         g_wh[WTOT];
__device__ __nv_bfloat16  g_wl[WTOT];
__device__ __half g_x  [(size_t)NN * HH];
__device__ __half g_h0 [(size_t)NN * HH];
__device__ __half g_hi [(size_t)NN * HH];
__device__ __half g_hs [(size_t)16384 * HH];
__device__ float g_cell[(size_t)NN * HH];
__device__ float g_iou [(size_t)NLEAF * 1536];    // also holds [n,2048] internal
__device__ float g_fh  [(size_t)NLEAF * HH];
__device__ float g_part[(size_t)512 * HH];
__device__ float g_cs  [HH];

// ---------------- portable PTX helpers (sm_80+ only) ----------------
__device__ __forceinline__ void mma_f16(float* c, const uint32_t* a, const uint32_t* b) {
    asm volatile(
        "mma.sync.aligned.m16n8k16.row.col.f32.f16.f16.f32 "
        "{%0,%1,%2,%3}, {%4,%5,%6,%7}, {%8,%9}, {%0,%1,%2,%3};"
        : "+f"(c[0]), "+f"(c[1]), "+f"(c[2]), "+f"(c[3])
        : "r"(a[0]), "r"(a[1]), "r"(a[2]), "r"(a[3]), "r"(b[0]), "r"(b[1]));
}
__device__ __forceinline__ void mma_bf16(float* c, const uint32_t* a, const uint32_t* b) {
    asm volatile(
        "mma.sync.aligned.m16n8k16.row.col.f32.bf16.bf16.f32 "
        "{%0,%1,%2,%3}, {%4,%5,%6,%7}, {%8,%9}, {%0,%1,%2,%3};"
        : "+f"(c[0]), "+f"(c[1]), "+f"(c[2]), "+f"(c[3])
        : "r"(a[0]), "r"(a[1]), "r"(a[2]), "r"(a[3]), "r"(b[0]), "r"(b[1]));
}
// fp16x2 reg -> bf16x2 reg (element positions preserved)
__device__ __forceinline__ uint32_t h2bf2(uint32_t h) {
    __half2 hv = *reinterpret_cast<__half2*>(&h);
    float2 f = __half22float2(hv);
    uint32_t r;
    asm("cvt.rn.bf16x2.f32 %0, %1, %2;" : "=r"(r) : "f"(f.y), "f"(f.x));
    return r;
}
__device__ __forceinline__ void cp16z(uint16_t* dst, const void* src, bool pred) {
    uint32_t d = (uint32_t)__cvta_generic_to_shared(dst);
    int sz = pred ? 16 : 0;
    asm volatile("cp.async.cg.shared.global [%0], [%1], 16, %2;" :: "r"(d), "l"(src), "r"(sz));
}
__device__ __forceinline__ void cp_commit() { asm volatile("cp.async.commit_group;" ::: "memory"); }
__device__ __forceinline__ void cp_wait2()  { asm volatile("cp.async.wait_group 2;"  ::: "memory"); }

// ---------------- mma.sync GEMM ------------------------------------------
// C = [A1@B1^T (+ A2@B2^T)] (+bias)(+relu).
// A: fp16. B: fp16 hi + bf16 lo. 2 passes: f16(A,Bh) + bf16(cvt(A),Bl).
// K = 512 per pass. CTA tile 128x128, 8 warps (2m x 4n), warp tile 64x32,
// K chunk 16. 4-stage cp.async pipeline, ONE barrier per chunk.
#define ASTR 24
#define TE   3072       // 128*24 elems per tile
#define STGE 9216       // 3 tiles per stage (18432 B)

template <bool RELU, bool HOUT>
__global__ __launch_bounds__(256, 2) void gemm_mma(
    const __half* __restrict__ A1,
    const __half* __restrict__ B1h, const __nv_bfloat16* __restrict__ B1l,
    const __half* __restrict__ A2,
    const __half* __restrict__ B2h, const __nv_bfloat16* __restrict__ B2l,
    const float* __restrict__ bias,
    float* __restrict__ Cf, __half* __restrict__ Chf,
    int M, int Ntot)
{
    extern __shared__ uint16_t sm16[];
    const int t    = threadIdx.x;
    const int lane = t & 31, wid = t >> 5;
    const int q = lane >> 2, p = lane & 3;
    const int wm = wid >> 2, wn = wid & 3;       // 2 x 4 warps, tile 64x32
    const int bm = blockIdx.y * 128;
    const int bn = blockIdx.x * 128;

    const int r  = t >> 1;          // staging row 0..127
    const int hf = t & 1;           // 8-elem half

    const int npass = (A2 != nullptr) ? 2 : 1;
    const int CT = npass * 32;

    float acc[4][4][4];
#pragma unroll
    for (int im = 0; im < 4; ++im)
#pragma unroll
        for (int in = 0; in < 4; ++in)
#pragma unroll
            for (int k = 0; k < 4; ++k) acc[im][in][k] = 0.f;

    auto stage = [&](int cc) {
        const int pass = cc >> 5, k0 = (cc & 31) * 16;
        const __half* A = pass ? A2 : A1;
        const __half* Bh = pass ? B2h : B1h;
        const __nv_bfloat16* Bl = pass ? B2l : B1l;
        uint16_t* stg = sm16 + (cc & 3) * STGE;
        const bool pa = (bm + r < M);
        const size_t asrc = (size_t)(bm + r) * 512 + k0 + hf * 8;
        const size_t bsrc = (size_t)(bn + r) * 512 + k0 + hf * 8;
        uint16_t* dst = stg + r * ASTR + hf * 8;
        cp16z(dst,          A  + asrc, pa);
        cp16z(dst + TE,     Bh + bsrc, true);
        cp16z(dst + 2 * TE, Bl + bsrc, true);
    };

    stage(0); cp_commit();
    if (CT > 1) { stage(1); cp_commit(); }

    for (int c = 0; c < CT; ++c) {
        if (c + 2 < CT) stage(c + 2);
        cp_commit();
        cp_wait2();
        __syncthreads();

        const uint16_t* stg = sm16 + (c & 3) * STGE;
        const uint16_t* AT = stg;
        const uint16_t* BH = stg + TE;
        const uint16_t* BL = stg + 2 * TE;

        uint32_t bh[4][2], bl[4][2];
#pragma unroll
        for (int in = 0; in < 4; ++in) {
            int off = (wn * 32 + in * 8 + q) * ASTR + 2 * p;
            bh[in][0] = *(const uint32_t*)(BH + off);
            bh[in][1] = *(const uint32_t*)(BH + off + 8);
            bl[in][0] = *(const uint32_t*)(BL + off);
            bl[in][1] = *(const uint32_t*)(BL + off + 8);
        }
#pragma unroll
        for (int im = 0; im < 4; ++im) {
            int off = (wm * 64 + im * 16 + q) * ASTR + 2 * p;
            uint32_t ah[4], abf[4];
            ah[0] = *(const uint32_t*)(AT + off);
            ah[1] = *(const uint32_t*)(AT + off + 8 * ASTR);
            ah[2] = *(const uint32_t*)(AT + off + 8);
            ah[3] = *(const uint32_t*)(AT + off + 8 * ASTR + 8);
            abf[0] = h2bf2(ah[0]);
            abf[1] = h2bf2(ah[1]);
            abf[2] = h2bf2(ah[2]);
            abf[3] = h2bf2(ah[3]);
            // pass-separated: same-acc RAW distance = 4 MMAs
#pragma unroll
            for (int in = 0; in < 4; ++in) mma_f16 (acc[im][in], ah,  bh[in]);
#pragma unroll
            for (int in = 0; in < 4; ++in) mma_bf16(acc[im][in], abf, bl[in]);
        }
    }

    // ---- epilogue
#pragma unroll
    for (int im = 0; im < 4; ++im) {
#pragma unroll
        for (int in = 0; in < 4; ++in) {
            int row = bm + wm * 64 + im * 16 + q;
            int col = bn + wn * 32 + in * 8 + 2 * p;
            float b0 = 0.f, b1 = 0.f;
            if (bias) { b0 = bias[col]; b1 = bias[col + 1]; }
            float c0 = acc[im][in][0] + b0;
            float c1 = acc[im][in][1] + b1;
            float c2 = acc[im][in][2] + b0;
            float c3 = acc[im][in][3] + b1;
            if (RELU) {
                c0 = c0 > 0.f ? c0 : 0.f;  c1 = c1 > 0.f ? c1 : 0.f;
                c2 = c2 > 0.f ? c2 : 0.f;  c3 = c3 > 0.f ? c3 : 0.f;
            }
            if (HOUT) {
                if (row < M) {
                    __half2 hv = __floats2half2_rn(c0, c1);
                    *(uint32_t*)&Chf[(size_t)row * Ntot + col] = *(uint32_t*)&hv;
                }
                if (row + 8 < M) {
                    __half2 hv = __floats2half2_rn(c2, c3);
                    *(uint32_t*)&Chf[(size_t)(row + 8) * Ntot + col] = *(uint32_t*)&hv;
                }
            } else {
                if (row < M)
                    *(float2*)&Cf[(size_t)row * Ntot + col] = make_float2(c0, c1);
                if (row + 8 < M)
                    *(float2*)&Cf[(size_t)(row + 8) * Ntot + col] = make_float2(c2, c3);
            }
        }
    }
}

// ---------------- conversions ---------------------------------------------
// W: [512, Ncols] fp32 row-major -> T[h|l]: [Ncols, 512]; hi fp16, lo bf16
__global__ void conv_w(const float* __restrict__ W,
                       __half* __restrict__ Th, __nv_bfloat16* __restrict__ Tl,
                       int Ncols)
{
    int idx = blockIdx.x * blockDim.x + threadIdx.x;
    if (idx >= 512 * Ncols) return;
    int n = idx >> 9, k = idx & 511;
    float v = W[(size_t)k * Ncols + n];
    __half h = __float2half(v);
    Th[idx] = h;
    Tl[idx] = __float2bfloat16(v - __half2float(h));
}

__global__ void conv_x(const float* __restrict__ X, __half* __restrict__ Xh)
{
    size_t idx = (size_t)blockIdx.x * blockDim.x + threadIdx.x;
    if (idx >= (size_t)NN * HH) return;
    Xh[idx] = __float2half(X[idx]);
}

// ---------------- pointwise kernels ---------------------------------------
__device__ __forceinline__ float sigm(float x) { return 1.f / (1.f + expf(-x)); }

__global__ void hsum_kernel(const __half* __restrict__ H,
                            __half* __restrict__ S, int n, int sc)
{
    int idx = blockIdx.x * blockDim.x + threadIdx.x;
    if (idx >= n * HH) return;
    int r = idx >> 9, j = idx & 511;
    size_t base = (size_t)(sc + 4 * r) * HH + j;
    float s = 0.f;
#pragma unroll
    for (int k = 0; k < 4; ++k) s += __half2float(H[base + k * HH]);
    S[idx] = __float2half(s);
}

__global__ void leaf_pw(const float* __restrict__ iou,
                        const float* __restrict__ bix, const float* __restrict__ bih,
                        __half* __restrict__ H, float* __restrict__ cell)
{
    int idx = blockIdx.x * blockDim.x + threadIdx.x;
    if (idx >= NLEAF * HH) return;
    int r = idx >> 9, j = idx & 511;
    const float* row = iou + (size_t)r * 1536;
    float i = sigm (row[j]        + bix[j]        + bih[j]);
    float o = sigm (row[512 + j]  + bix[512 + j]  + bih[512 + j]);
    float u = tanhf(row[1024 + j] + bix[1024 + j] + bih[1024 + j]);
    float c = i * u;
    size_t g = (size_t)(SLEAF + r) * HH + j;
    cell[g] = c;
    H[g] = __float2half(o * tanhf(c));
}

// combined buffer row layout: [i(512) | o(512) | u(512) | fx(512)], stride 2048
__global__ void int_pw(const float* __restrict__ cio, const float* __restrict__ fh,
                       const float* __restrict__ bix, const float* __restrict__ bih,
                       const float* __restrict__ bfx, const float* __restrict__ bfh,
                       __half* __restrict__ H, float* __restrict__ cell,
                       int n, int s, int sc)
{
    int idx = blockIdx.x * blockDim.x + threadIdx.x;
    if (idx >= n * HH) return;
    int r = idx >> 9, j = idx & 511;
    const float* row = cio + (size_t)r * 2048;
    float i = sigm (row[j]        + bix[j]        + bih[j]);
    float o = sigm (row[512 + j]  + bix[512 + j]  + bih[512 + j]);
    float u = tanhf(row[1024 + j] + bix[1024 + j] + bih[1024 + j]);
    float fxv = row[1536 + j] + bfx[j] + bfh[j];
    float acc = i * u;
#pragma unroll
    for (int k = 0; k < 4; ++k) {
        float f = sigm(fxv + fh[(size_t)(4 * r + k) * HH + j]);
        acc += f * cell[(size_t)(sc + 4 * r + k) * HH + j];
    }
    size_t g = (size_t)(s + r) * HH + j;
    cell[g] = acc;
    H[g] = __float2half(o * tanhf(acc));
}

__global__ void colsum_part(const __half* __restrict__ H, float* __restrict__ part)
{
    int b = blockIdx.x;
    const int rows_per = (NN + 511) / 512;
    int r0 = b * rows_per;
    int r1 = r0 + rows_per; if (r1 > NN) r1 = NN;
    for (int j = threadIdx.x; j < HH; j += blockDim.x) {
        float s = 0.f;
        for (int r = r0; r < r1; ++r) s += __half2float(H[(size_t)r * HH + j]);
        part[(size_t)b * HH + j] = s;
    }
}

__global__ void colsum_final(const float* __restrict__ part, float* __restrict__ cs)
{
    int j = blockIdx.x * blockDim.x + threadIdx.x;
    if (j >= HH) return;
    float acc = 0.f;
    for (int b = 0; b < 512; ++b) acc += part[(size_t)b * HH + j];
    cs[j] = acc;
}

__global__ void tree_kernel(const float* __restrict__ cs, const float* __restrict__ W_out,
                            const float* __restrict__ b_out, float* __restrict__ out)
{
    int j = threadIdx.x;
    float acc = (float)NN * b_out[j];
    for (int k = 0; k < HH; ++k) acc += cs[k] * W_out[(size_t)k * OUTF + j];
    out[j] = acc;
}

// ---------------- driver ---------------------------------------------------
static void* symv(const void* s) { void* p = nullptr; cudaGetSymbolAddress(&p, s); return p; }

extern "C" void kernel_launch(void* const* d_in, const int* in_sizes, int n_in,
                              void* d_out, int out_size)
{
    (void)in_sizes; (void)n_in; (void)out_size;
    const float* x      = (const float*)d_in[0];
    const float* W_in   = (const float*)d_in[8];
    const float* b_in   = (const float*)d_in[9];
    const float* W_ioux = (const float*)d_in[10];
    const float* b_ioux = (const float*)d_in[11];
    const float* W_iouh = (const float*)d_in[12];
    const float* b_iouh = (const float*)d_in[13];
    const float* W_fx   = (const float*)d_in[14];
    const float* b_fx   = (const float*)d_in[15];
    const float* W_fh   = (const float*)d_in[16];
    const float* b_fh   = (const float*)d_in[17];
    const float* W_out  = (const float*)d_in[18];
    const float* b_out  = (const float*)d_in[19];
    float* out = (float*)d_out;

    __half* wh          = (__half*)symv(g_wh);
    __nv_bfloat16* wl   = (__nv_bfloat16*)symv(g_wl);
    __half* xh  = (__half*)symv(g_x);
    __half* h0  = (__half*)symv(g_h0);
    __half* hi  = (__half*)symv(g_hi);
    __half* hs  = (__half*)symv(g_hs);
    float* cell = (float*)symv(g_cell);
    float* iou  = (float*)symv(g_iou);
    float* fh   = (float*)symv(g_fh);
    float* part = (float*)symv(g_part);
    float* cs   = (float*)symv(g_cs);

    const int SMB = 4 * STGE * 2;  // 73728 B (4 stages, 3 tiles)
    cudaFuncSetAttribute(gemm_mma<false,false>, cudaFuncAttributeMaxDynamicSharedMemorySize, SMB);
    cudaFuncSetAttribute(gemm_mma<true,true>,   cudaFuncAttributeMaxDynamicSharedMemorySize, SMB);

    // ---- conversions (transpose + fp16/bf16 hi/lo split)
    conv_w<<<(512 * 512 + 255) / 256, 256>>>(W_in, wh + OFF_WIN, wl + OFF_WIN, 512);
    conv_w<<<(512 * 1536 + 255) / 256, 256>>>(W_ioux,              wh + OFF_CX0, wl + OFF_CX0, 1536);
    conv_w<<<(512 * 1536 + 255) / 256, 256>>>(W_ioux + 512 * 1536, wh + OFF_CX1, wl + OFF_CX1, 1536);
    conv_w<<<(512 * 512 + 255) / 256, 256>>>(W_fx,             wh + OFF_CX0 + FXROW, wl + OFF_CX0 + FXROW, 512);
    conv_w<<<(512 * 512 + 255) / 256, 256>>>(W_fx + 512 * 512, wh + OFF_CX1 + FXROW, wl + OFF_CX1 + FXROW, 512);
    conv_w<<<(512 * 1536 + 255) / 256, 256>>>(W_iouh,              wh + OFF_CH0, wl + OFF_CH0, 1536);
    conv_w<<<(512 * 1536 + 255) / 256, 256>>>(W_iouh + 512 * 1536, wh + OFF_CH1, wl + OFF_CH1, 1536);
    cudaMemsetAsync(wh + OFF_CH0 + FXROW, 0, 512 * 512 * 2);
    cudaMemsetAsync(wl + OFF_CH0 + FXROW, 0, 512 * 512 * 2);
    cudaMemsetAsync(wh + OFF_CH1 + FXROW, 0, 512 * 512 * 2);
    cudaMemsetAsync(wl + OFF_CH1 + FXROW, 0, 512 * 512 * 2);
    conv_w<<<(512 * 512 + 255) / 256, 256>>>(W_fh,             wh + OFF_FH0, wl + OFF_FH0, 512);
    conv_w<<<(512 * 512 + 255) / 256, 256>>>(W_fh + 512 * 512, wh + OFF_FH1, wl + OFF_FH1, 512);
    conv_w<<<(512 * 256 + 255) / 256, 256>>>(W_out, wh + OFF_WOUT, wl + OFF_WOUT, 256);
    conv_x<<<(int)(((size_t)NN * HH + 255) / 256), 256>>>(x, xh);

    const int MT_ALL = (NN + 127) / 128;   // 683

    // ---- input projection: h0 = relu(x @ W_in + b_in), fp16 out
    gemm_mma<true,true><<<dim3(4, MT_ALL), 256, SMB>>>(
        xh, wh + OFF_WIN, wl + OFF_WIN,
        nullptr, nullptr, nullptr,
        b_in, nullptr, h0, NN, HH);

    const int offCX[2] = {OFF_CX0, OFF_CX1};
    const int offCH[2] = {OFF_CH0, OFF_CH1};
    const int offFH[2] = {OFF_FH0, OFF_FH1};

    for (int l = 0; l < 2; ++l) {
        __half* hin  = (l == 0) ? h0 : hi;
        __half* hout = (l == 0) ? hi : h0;
        const float* Bix = b_ioux + (size_t)l * 1536;
        const float* Bih = b_iouh + (size_t)l * 1536;
        const float* Bfx = b_fx   + (size_t)l * HH;
        const float* Bfh = b_fh   + (size_t)l * HH;

        // leaf level: iou only (rows 0..1535 of CX = W_ioux), stride 1536
        gemm_mma<false,false><<<dim3(12, NLEAF / 128), 256, SMB>>>(
            hin + (size_t)SLEAF * HH, wh + offCX[l], wl + offCX[l],
            nullptr, nullptr, nullptr,
            nullptr, iou, nullptr, NLEAF, 1536);
        leaf_pw<<<(NLEAF * HH) / 256, 256>>>(iou, Bix, Bih, hout, cell);

        for (int d = 7; d >= 0; --d) {
            int s  = LS[d];
            int n  = LS[d + 1] - LS[d];
            int sc = LS[d + 1];
            int mt  = (n + 127) / 128;
            int mt4 = (4 * n + 127) / 128;
            int nblk_pw = (n * HH + 255) / 256;

            hsum_kernel<<<nblk_pw, 256>>>(hout, hs, n, sc);
            // combined iou + fx: C[n, 2048] = hin@[Wix|Wfx] + hsum@[Wih|0]
            gemm_mma<false,false><<<dim3(16, mt), 256, SMB>>>(
                hin + (size_t)s * HH, wh + offCX[l], wl + offCX[l],
                hs, wh + offCH[l], wl + offCH[l],
                nullptr, iou, nullptr, n, 2048);
            gemm_mma<false,false><<<dim3(4, mt4), 256, SMB>>>(
                hout + (size_t)sc * HH, wh + offFH[l], wl + offFH[l],
                nullptr, nullptr, nullptr,
                nullptr, fh, nullptr, 4 * n, HH);
            int_pw<<<nblk_pw, 256>>>(iou, fh, Bix, Bih, Bfx, Bfh,
                                     hout, cell, n, s, sc);
        }
    }

    // node_emb = h0 @ W_out + b_out
    gemm_mma<false,false><<<dim3(2, MT_ALL), 256, SMB>>>(
        h0, wh + OFF_WOUT, wl + OFF_WOUT,
        nullptr, nullptr, nullptr,
        b_out, out, nullptr, NN, OUTF);

    // tree_emb
    colsum_part<<<512, 256>>>(h0, part);
    colsum_final<<<2, 256>>>(part, cs);
    tree_kernel<<<1, 256>>>(cs, W_out, b_out, out + (size_t)NN * OUTF);
}

// round 10
// speedup vs baseline: 2.1093x; 1.3972x over previous
#include <cuda_runtime.h>
#include <cuda_bf16.h>
#include <cuda_fp16.h>
#include <cstdint>
#include <math.h>

// ---------------- problem constants ----------------
#define NN     87381
#define HH     512
#define OUTF   256
#define NLEAF  65536
#define SLEAF  21845
static const int LS[10] = {0,1,5,21,85,341,1365,5461,21845,87381};

// converted weight offsets (elements), all [N,K=512] row-major fp16
// CX_l = [W_ioux_l (1536 rows) | W_fx_l (512 rows)]  (2048 x 512)
// CH_l = [W_iouh_l (1536 rows) | zeros  (512 rows)]  (2048 x 512)
#define OFF_WIN    0
#define OFF_CX0    262144
#define OFF_CX1    1310720
#define OFF_CH0    2359296
#define OFF_CH1    3407872
#define OFF_FH0    4456448
#define OFF_FH1    4718592
#define OFF_WOUT   4980736
#define WTOT       5111808
#define FXROW      786432     // 1536*512: offset of FX part within CX

// ---------------- scratch (device globals; no allocation) ----------
__device__ __half g_wh[WTOT];
__device__ __half g_x  [(size_t)NN * HH];
__device__ __half g_h0 [(size_t)NN * HH];
__device__ __half g_hi [(size_t)NN * HH];
__device__ __half g_hs [(size_t)16384 * HH];
__device__ float g_cell[(size_t)NN * HH];
__device__ float g_iou [(size_t)NLEAF * 1536];    // also holds [n,2048] internal
__device__ float g_fh  [(size_t)NLEAF * HH];
__device__ float g_part[(size_t)512 * HH];
__device__ float g_cs  [HH];

// ---------------- portable PTX helpers (sm_80+ only) ----------------
__device__ __forceinline__ void mma_f16(float* c, const uint32_t* a, const uint32_t* b) {
    asm volatile(
        "mma.sync.aligned.m16n8k16.row.col.f32.f16.f16.f32 "
        "{%0,%1,%2,%3}, {%4,%5,%6,%7}, {%8,%9}, {%0,%1,%2,%3};"
        : "+f"(c[0]), "+f"(c[1]), "+f"(c[2]), "+f"(c[3])
        : "r"(a[0]), "r"(a[1]), "r"(a[2]), "r"(a[3]), "r"(b[0]), "r"(b[1]));
}
__device__ __forceinline__ void cp16z(uint16_t* dst, const void* src, bool pred) {
    uint32_t d = (uint32_t)__cvta_generic_to_shared(dst);
    int sz = pred ? 16 : 0;
    asm volatile("cp.async.cg.shared.global [%0], [%1], 16, %2;" :: "r"(d), "l"(src), "r"(sz));
}
__device__ __forceinline__ void cp_commit() { asm volatile("cp.async.commit_group;" ::: "memory"); }
__device__ __forceinline__ void cp_wait2()  { asm volatile("cp.async.wait_group 2;"  ::: "memory"); }

// ---------------- mma.sync GEMM ------------------------------------------
// C = [A1@B1^T (+ A2@B2^T)] (+bias)(+relu). A, B fp16, fp32 accumulate.
// Single-pass fp16. K = 512 per pass. CTA tile 128x128, 8 warps (2m x 4n),
// warp tile 64x32, K chunk 16. 4-stage cp.async pipeline, ONE barrier/chunk.
#define ASTR 24
#define TE   3072       // 128*24 elems per tile
#define STGE 6144       // 2 tiles per stage (12288 B)

template <bool RELU, bool HOUT>
__global__ __launch_bounds__(256, 2) void gemm_mma(
    const __half* __restrict__ A1, const __half* __restrict__ B1,
    const __half* __restrict__ A2, const __half* __restrict__ B2,
    const float* __restrict__ bias,
    float* __restrict__ Cf, __half* __restrict__ Chf,
    int M, int Ntot)
{
    extern __shared__ uint16_t sm16[];
    const int t    = threadIdx.x;
    const int lane = t & 31, wid = t >> 5;
    const int q = lane >> 2, p = lane & 3;
    const int wm = wid >> 2, wn = wid & 3;       // 2 x 4 warps, tile 64x32
    const int bm = blockIdx.y * 128;
    const int bn = blockIdx.x * 128;

    const int r  = t >> 1;          // staging row 0..127
    const int hf = t & 1;           // 8-elem half

    const int npass = (A2 != nullptr) ? 2 : 1;
    const int CT = npass * 32;

    float acc[4][4][4];
#pragma unroll
    for (int im = 0; im < 4; ++im)
#pragma unroll
        for (int in = 0; in < 4; ++in)
#pragma unroll
            for (int k = 0; k < 4; ++k) acc[im][in][k] = 0.f;

    auto stage = [&](int cc) {
        const int pass = cc >> 5, k0 = (cc & 31) * 16;
        const __half* A = pass ? A2 : A1;
        const __half* B = pass ? B2 : B1;
        uint16_t* stg = sm16 + (cc & 3) * STGE;
        const bool pa = (bm + r < M);
        const size_t asrc = (size_t)(bm + r) * 512 + k0 + hf * 8;
        const size_t bsrc = (size_t)(bn + r) * 512 + k0 + hf * 8;
        uint16_t* dst = stg + r * ASTR + hf * 8;
        cp16z(dst,      A + asrc, pa);
        cp16z(dst + TE, B + bsrc, true);
    };

    stage(0); cp_commit();
    if (CT > 1) { stage(1); cp_commit(); }

    for (int c = 0; c < CT; ++c) {
        if (c + 2 < CT) stage(c + 2);
        cp_commit();
        cp_wait2();
        __syncthreads();

        const uint16_t* stg = sm16 + (c & 3) * STGE;
        const uint16_t* AT = stg;
        const uint16_t* BT = stg + TE;

        uint32_t bh[4][2];
#pragma unroll
        for (int in = 0; in < 4; ++in) {
            int off = (wn * 32 + in * 8 + q) * ASTR + 2 * p;
            bh[in][0] = *(const uint32_t*)(BT + off);
            bh[in][1] = *(const uint32_t*)(BT + off + 8);
        }
#pragma unroll
        for (int im = 0; im < 4; ++im) {
            int off = (wm * 64 + im * 16 + q) * ASTR + 2 * p;
            uint32_t ah[4];
            ah[0] = *(const uint32_t*)(AT + off);
            ah[1] = *(const uint32_t*)(AT + off + 8 * ASTR);
            ah[2] = *(const uint32_t*)(AT + off + 8);
            ah[3] = *(const uint32_t*)(AT + off + 8 * ASTR + 8);
#pragma unroll
            for (int in = 0; in < 4; ++in) mma_f16(acc[im][in], ah, bh[in]);
        }
    }

    // ---- epilogue
#pragma unroll
    for (int im = 0; im < 4; ++im) {
#pragma unroll
        for (int in = 0; in < 4; ++in) {
            int row = bm + wm * 64 + im * 16 + q;
            int col = bn + wn * 32 + in * 8 + 2 * p;
            float b0 = 0.f, b1 = 0.f;
            if (bias) { b0 = bias[col]; b1 = bias[col + 1]; }
            float c0 = acc[im][in][0] + b0;
            float c1 = acc[im][in][1] + b1;
            float c2 = acc[im][in][2] + b0;
            float c3 = acc[im][in][3] + b1;
            if (RELU) {
                c0 = c0 > 0.f ? c0 : 0.f;  c1 = c1 > 0.f ? c1 : 0.f;
                c2 = c2 > 0.f ? c2 : 0.f;  c3 = c3 > 0.f ? c3 : 0.f;
            }
            if (HOUT) {
                if (row < M) {
                    __half2 hv = __floats2half2_rn(c0, c1);
                    *(uint32_t*)&Chf[(size_t)row * Ntot + col] = *(uint32_t*)&hv;
                }
                if (row + 8 < M) {
                    __half2 hv = __floats2half2_rn(c2, c3);
                    *(uint32_t*)&Chf[(size_t)(row + 8) * Ntot + col] = *(uint32_t*)&hv;
                }
            } else {
                if (row < M)
                    *(float2*)&Cf[(size_t)row * Ntot + col] = make_float2(c0, c1);
                if (row + 8 < M)
                    *(float2*)&Cf[(size_t)(row + 8) * Ntot + col] = make_float2(c2, c3);
            }
        }
    }
}

// ---------------- conversions ---------------------------------------------
// W: [512, Ncols] fp32 row-major -> T: [Ncols, 512] fp16
__global__ void conv_w(const float* __restrict__ W,
                       __half* __restrict__ Th, int Ncols)
{
    int idx = blockIdx.x * blockDim.x + threadIdx.x;
    if (idx >= 512 * Ncols) return;
    int n = idx >> 9, k = idx & 511;
    Th[idx] = __float2half(W[(size_t)k * Ncols + n]);
}

__global__ void conv_x(const float* __restrict__ X, __half* __restrict__ Xh)
{
    size_t idx = (size_t)blockIdx.x * blockDim.x + threadIdx.x;
    if (idx >= (size_t)NN * HH) return;
    Xh[idx] = __float2half(X[idx]);
}

// ---------------- pointwise kernels ---------------------------------------
__device__ __forceinline__ float sigm(float x) { return 1.f / (1.f + expf(-x)); }

__global__ void hsum_kernel(const __half* __restrict__ H,
                            __half* __restrict__ S, int n, int sc)
{
    int idx = blockIdx.x * blockDim.x + threadIdx.x;
    if (idx >= n * HH) return;
    int r = idx >> 9, j = idx & 511;
    size_t base = (size_t)(sc + 4 * r) * HH + j;
    float s = 0.f;
#pragma unroll
    for (int k = 0; k < 4; ++k) s += __half2float(H[base + k * HH]);
    S[idx] = __float2half(s);
}

__global__ void leaf_pw(const float* __restrict__ iou,
                        const float* __restrict__ bix, const float* __restrict__ bih,
                        __half* __restrict__ H, float* __restrict__ cell)
{
    int idx = blockIdx.x * blockDim.x + threadIdx.x;
    if (idx >= NLEAF * HH) return;
    int r = idx >> 9, j = idx & 511;
    const float* row = iou + (size_t)r * 1536;
    float i = sigm (row[j]        + bix[j]        + bih[j]);
    float o = sigm (row[512 + j]  + bix[512 + j]  + bih[512 + j]);
    float u = tanhf(row[1024 + j] + bix[1024 + j] + bih[1024 + j]);
    float c = i * u;
    size_t g = (size_t)(SLEAF + r) * HH + j;
    cell[g] = c;
    H[g] = __float2half(o * tanhf(c));
}

// combined buffer row layout: [i(512) | o(512) | u(512) | fx(512)], stride 2048
__global__ void int_pw(const float* __restrict__ cio, const float* __restrict__ fh,
                       const float* __restrict__ bix, const float* __restrict__ bih,
                       const float* __restrict__ bfx, const float* __restrict__ bfh,
                       __half* __restrict__ H, float* __restrict__ cell,
                       int n, int s, int sc)
{
    int idx = blockIdx.x * blockDim.x + threadIdx.x;
    if (idx >= n * HH) return;
    int r = idx >> 9, j = idx & 511;
    const float* row = cio + (size_t)r * 2048;
    float i = sigm (row[j]        + bix[j]        + bih[j]);
    float o = sigm (row[512 + j]  + bix[512 + j]  + bih[512 + j]);
    float u = tanhf(row[1024 + j] + bix[1024 + j] + bih[1024 + j]);
    float fxv = row[1536 + j] + bfx[j] + bfh[j];
    float acc = i * u;
#pragma unroll
    for (int k = 0; k < 4; ++k) {
        float f = sigm(fxv + fh[(size_t)(4 * r + k) * HH + j]);
        acc += f * cell[(size_t)(sc + 4 * r + k) * HH + j];
    }
    size_t g = (size_t)(s + r) * HH + j;
    cell[g] = acc;
    H[g] = __float2half(o * tanhf(acc));
}

__global__ void colsum_part(const __half* __restrict__ H, float* __restrict__ part)
{
    int b = blockIdx.x;
    const int rows_per = (NN + 511) / 512;
    int r0 = b * rows_per;
    int r1 = r0 + rows_per; if (r1 > NN) r1 = NN;
    for (int j = threadIdx.x; j < HH; j += blockDim.x) {
        float s = 0.f;
        for (int r = r0; r < r1; ++r) s += __half2float(H[(size_t)r * HH + j]);
        part[(size_t)b * HH + j] = s;
    }
}

__global__ void colsum_final(const float* __restrict__ part, float* __restrict__ cs)
{
    int j = blockIdx.x * blockDim.x + threadIdx.x;
    if (j >= HH) return;
    float acc = 0.f;
    for (int b = 0; b < 512; ++b) acc += part[(size_t)b * HH + j];
    cs[j] = acc;
}

__global__ void tree_kernel(const float* __restrict__ cs, const float* __restrict__ W_out,
                            const float* __restrict__ b_out, float* __restrict__ out)
{
    int j = threadIdx.x;
    float acc = (float)NN * b_out[j];
    for (int k = 0; k < HH; ++k) acc += cs[k] * W_out[(size_t)k * OUTF + j];
    out[j] = acc;
}

// ---------------- driver ---------------------------------------------------
static void* symv(const void* s) { void* p = nullptr; cudaGetSymbolAddress(&p, s); return p; }

extern "C" void kernel_launch(void* const* d_in, const int* in_sizes, int n_in,
                              void* d_out, int out_size)
{
    (void)in_sizes; (void)n_in; (void)out_size;
    const float* x      = (const float*)d_in[0];
    const float* W_in   = (const float*)d_in[8];
    const float* b_in   = (const float*)d_in[9];
    const float* W_ioux = (const float*)d_in[10];
    const float* b_ioux = (const float*)d_in[11];
    const float* W_iouh = (const float*)d_in[12];
    const float* b_iouh = (const float*)d_in[13];
    const float* W_fx   = (const float*)d_in[14];
    const float* b_fx   = (const float*)d_in[15];
    const float* W_fh   = (const float*)d_in[16];
    const float* b_fh   = (const float*)d_in[17];
    const float* W_out  = (const float*)d_in[18];
    const float* b_out  = (const float*)d_in[19];
    float* out = (float*)d_out;

    __half* wh  = (__half*)symv(g_wh);
    __half* xh  = (__half*)symv(g_x);
    __half* h0  = (__half*)symv(g_h0);
    __half* hi  = (__half*)symv(g_hi);
    __half* hs  = (__half*)symv(g_hs);
    float* cell = (float*)symv(g_cell);
    float* iou  = (float*)symv(g_iou);
    float* fh   = (float*)symv(g_fh);
    float* part = (float*)symv(g_part);
    float* cs   = (float*)symv(g_cs);

    const int SMB = 4 * STGE * 2;  // 49152 B (4 stages, 2 tiles)
    cudaFuncSetAttribute(gemm_mma<false,false>, cudaFuncAttributeMaxDynamicSharedMemorySize, SMB);
    cudaFuncSetAttribute(gemm_mma<true,true>,   cudaFuncAttributeMaxDynamicSharedMemorySize, SMB);

    // ---- conversions (transpose + fp16)
    conv_w<<<(512 * 512 + 255) / 256, 256>>>(W_in, wh + OFF_WIN, 512);
    conv_w<<<(512 * 1536 + 255) / 256, 256>>>(W_ioux,              wh + OFF_CX0, 1536);
    conv_w<<<(512 * 1536 + 255) / 256, 256>>>(W_ioux + 512 * 1536, wh + OFF_CX1, 1536);
    conv_w<<<(512 * 512 + 255) / 256, 256>>>(W_fx,             wh + OFF_CX0 + FXROW, 512);
    conv_w<<<(512 * 512 + 255) / 256, 256>>>(W_fx + 512 * 512, wh + OFF_CX1 + FXROW, 512);
    conv_w<<<(512 * 1536 + 255) / 256, 256>>>(W_iouh,              wh + OFF_CH0, 1536);
    conv_w<<<(512 * 1536 + 255) / 256, 256>>>(W_iouh + 512 * 1536, wh + OFF_CH1, 1536);
    cudaMemsetAsync(wh + OFF_CH0 + FXROW, 0, 512 * 512 * 2);
    cudaMemsetAsync(wh + OFF_CH1 + FXROW, 0, 512 * 512 * 2);
    conv_w<<<(512 * 512 + 255) / 256, 256>>>(W_fh,             wh + OFF_FH0, 512);
    conv_w<<<(512 * 512 + 255) / 256, 256>>>(W_fh + 512 * 512, wh + OFF_FH1, 512);
    conv_w<<<(512 * 256 + 255) / 256, 256>>>(W_out, wh + OFF_WOUT, 256);
    conv_x<<<(int)(((size_t)NN * HH + 255) / 256), 256>>>(x, xh);

    const int MT_ALL = (NN + 127) / 128;   // 683

    // ---- input projection: h0 = relu(x @ W_in + b_in), fp16 out
    gemm_mma<true,true><<<dim3(4, MT_ALL), 256, SMB>>>(
        xh, wh + OFF_WIN, nullptr, nullptr,
        b_in, nullptr, h0, NN, HH);

    const int offCX[2] = {OFF_CX0, OFF_CX1};
    const int offCH[2] = {OFF_CH0, OFF_CH1};
    const int offFH[2] = {OFF_FH0, OFF_FH1};

    for (int l = 0; l < 2; ++l) {
        __half* hin  = (l == 0) ? h0 : hi;
        __half* hout = (l == 0) ? hi : h0;
        const float* Bix = b_ioux + (size_t)l * 1536;
        const float* Bih = b_iouh + (size_t)l * 1536;
        const float* Bfx = b_fx   + (size_t)l * HH;
        const float* Bfh = b_fh   + (size_t)l * HH;

        // leaf level: iou only (rows 0..1535 of CX = W_ioux), stride 1536
        gemm_mma<false,false><<<dim3(12, NLEAF / 128), 256, SMB>>>(
            hin + (size_t)SLEAF * HH, wh + offCX[l],
            nullptr, nullptr,
            nullptr, iou, nullptr, NLEAF, 1536);
        leaf_pw<<<(NLEAF * HH) / 256, 256>>>(iou, Bix, Bih, hout, cell);

        for (int d = 7; d >= 0; --d) {
            int s  = LS[d];
            int n  = LS[d + 1] - LS[d];
            int sc = LS[d + 1];
            int mt  = (n + 127) / 128;
            int mt4 = (4 * n + 127) / 128;
            int nblk_pw = (n * HH + 255) / 256;

            hsum_kernel<<<nblk_pw, 256>>>(hout, hs, n, sc);
            // combined iou + fx: C[n, 2048] = hin@[Wix|Wfx] + hsum@[Wih|0]
            gemm_mma<false,false><<<dim3(16, mt), 256, SMB>>>(
                hin + (size_t)s * HH, wh + offCX[l],
                hs, wh + offCH[l],
                nullptr, iou, nullptr, n, 2048);
            gemm_mma<false,false><<<dim3(4, mt4), 256, SMB>>>(
                hout + (size_t)sc * HH, wh + offFH[l],
                nullptr, nullptr,
                nullptr, fh, nullptr, 4 * n, HH);
            int_pw<<<nblk_pw, 256>>>(iou, fh, Bix, Bih, Bfx, Bfh,
                                     hout, cell, n, s, sc);
        }
    }

    // node_emb = h0 @ W_out + b_out
    gemm_mma<false,false><<<dim3(2, MT_ALL), 256, SMB>>>(
        h0, wh + OFF_WOUT, nullptr, nullptr,
        b_out, out, nullptr, NN, OUTF);

    // tree_emb
    colsum_part<<<512, 256>>>(h0, part);
    colsum_final<<<2, 256>>>(part, cs);
    tree_kernel<<<1, 256>>>(cs, W_out, b_out, out + (size_t)NN * OUTF);
}

// round 13
// speedup vs baseline: 2.2401x; 1.0620x over previous
#include <cuda_runtime.h>
#include <cuda_bf16.h>
#include <cuda_fp16.h>
#include <cstdint>
#include <math.h>

// ---------------- problem constants ----------------
#define NN     87381
#define HH     512
#define OUTF   256
#define NLEAF  65536
#define SLEAF  21845
static const int LS[10] = {0,1,5,21,85,341,1365,5461,21845,87381};

// converted weight offsets (elements), all [N,K=512] row-major fp16
// CX_l = [W_ioux_l (1536 rows) | W_fx_l (512 rows)]  (2048 x 512)
// CH_l = [W_iouh_l (1536 rows) | zeros  (512 rows)]  (2048 x 512)
#define OFF_WIN    0
#define OFF_CX0    262144
#define OFF_CX1    1310720
#define OFF_CH0    2359296
#define OFF_CH1    3407872
#define OFF_FH0    4456448
#define OFF_FH1    4718592
#define OFF_WOUT   4980736
#define WTOT       5111808
#define FXROW      786432     // 1536*512: offset of FX part within CX

// ---------------- scratch (device globals; no allocation) ----------
__device__ __half g_wh[WTOT];
__device__ __half g_x  [(size_t)NN * HH];
__device__ __half g_h0 [(size_t)NN * HH];
__device__ __half g_hi [(size_t)NN * HH];
__device__ __half g_hs [(size_t)16384 * HH];
__device__ float g_cell[(size_t)NN * HH];
__device__ float g_iou [(size_t)NLEAF * 1536];    // also holds [n,2048] internal
__device__ float g_fh  [(size_t)NLEAF * HH];
__device__ float g_part[(size_t)512 * HH];
__device__ float g_cs  [HH];

// ---------------- portable PTX helpers (sm_80+ only) ----------------
__device__ __forceinline__ void mma_f16(float* c, const uint32_t* a, const uint32_t* b) {
    asm volatile(
        "mma.sync.aligned.m16n8k16.row.col.f32.f16.f16.f32 "
        "{%0,%1,%2,%3}, {%4,%5,%6,%7}, {%8,%9}, {%0,%1,%2,%3};"
        : "+f"(c[0]), "+f"(c[1]), "+f"(c[2]), "+f"(c[3])
        : "r"(a[0]), "r"(a[1]), "r"(a[2]), "r"(a[3]), "r"(b[0]), "r"(b[1]));
}
__device__ __forceinline__ void cp16z(uint16_t* dst, const void* src, bool pred) {
    uint32_t d = (uint32_t)__cvta_generic_to_shared(dst);
    int sz = pred ? 16 : 0;
    asm volatile("cp.async.cg.shared.global [%0], [%1], 16, %2;" :: "r"(d), "l"(src), "r"(sz));
}
__device__ __forceinline__ void cp_commit() { asm volatile("cp.async.commit_group;" ::: "memory"); }
__device__ __forceinline__ void cp_wait2()  { asm volatile("cp.async.wait_group 2;"  ::: "memory"); }

#define ASTR 24
#define TE   3072       // 128*24 elems (A tile / 128-row B tile)

// ---------------- big GEMM: CTA 128x128, warp 64x32 ----------------------
#define STGE 6144       // 2 tiles per stage (12288 B)

template <bool RELU, bool HOUT>
__global__ __launch_bounds__(256, 2) void gemm_mma(
    const __half* __restrict__ A1, const __half* __restrict__ B1,
    const __half* __restrict__ A2, const __half* __restrict__ B2,
    const float* __restrict__ bias,
    float* __restrict__ Cf, __half* __restrict__ Chf,
    int M, int Ntot)
{
    extern __shared__ uint16_t sm16[];
    const int t    = threadIdx.x;
    const int lane = t & 31, wid = t >> 5;
    const int q = lane >> 2, p = lane & 3;
    const int wm = wid >> 2, wn = wid & 3;       // 2 x 4 warps, tile 64x32
    const int bm = blockIdx.y * 128;
    const int bn = blockIdx.x * 128;

    const int r  = t >> 1;
    const int hf = t & 1;

    const int npass = (A2 != nullptr) ? 2 : 1;
    const int CT = npass * 32;

    float acc[4][4][4];
#pragma unroll
    for (int im = 0; im < 4; ++im)
#pragma unroll
        for (int in = 0; in < 4; ++in)
#pragma unroll
            for (int k = 0; k < 4; ++k) acc[im][in][k] = 0.f;

    auto stage = [&](int cc) {
        const int pass = cc >> 5, k0 = (cc & 31) * 16;
        const __half* A = pass ? A2 : A1;
        const __half* B = pass ? B2 : B1;
        uint16_t* stg = sm16 + (cc & 3) * STGE;
        const bool pa = (bm + r < M);
        const size_t asrc = (size_t)(bm + r) * 512 + k0 + hf * 8;
        const size_t bsrc = (size_t)(bn + r) * 512 + k0 + hf * 8;
        uint16_t* dst = stg + r * ASTR + hf * 8;
        cp16z(dst,      A + asrc, pa);
        cp16z(dst + TE, B + bsrc, true);
    };

    stage(0); cp_commit();
    if (CT > 1) { stage(1); cp_commit(); }

    for (int c = 0; c < CT; ++c) {
        if (c + 2 < CT) stage(c + 2);
        cp_commit();
        cp_wait2();
        __syncthreads();

        const uint16_t* stg = sm16 + (c & 3) * STGE;
        const uint16_t* AT = stg;
        const uint16_t* BT = stg + TE;

        uint32_t bh[4][2];
#pragma unroll
        for (int in = 0; in < 4; ++in) {
            int off = (wn * 32 + in * 8 + q) * ASTR + 2 * p;
            bh[in][0] = *(const uint32_t*)(BT + off);
            bh[in][1] = *(const uint32_t*)(BT + off + 8);
        }
#pragma unroll
        for (int im = 0; im < 4; ++im) {
            int off = (wm * 64 + im * 16 + q) * ASTR + 2 * p;
            uint32_t ah[4];
            ah[0] = *(const uint32_t*)(AT + off);
            ah[1] = *(const uint32_t*)(AT + off + 8 * ASTR);
            ah[2] = *(const uint32_t*)(AT + off + 8);
            ah[3] = *(const uint32_t*)(AT + off + 8 * ASTR + 8);
#pragma unroll
            for (int in = 0; in < 4; ++in) mma_f16(acc[im][in], ah, bh[in]);
        }
    }

#pragma unroll
    for (int im = 0; im < 4; ++im) {
#pragma unroll
        for (int in = 0; in < 4; ++in) {
            int row = bm + wm * 64 + im * 16 + q;
            int col = bn + wn * 32 + in * 8 + 2 * p;
            float b0 = 0.f, b1 = 0.f;
            if (bias) { b0 = bias[col]; b1 = bias[col + 1]; }
            float c0 = acc[im][in][0] + b0;
            float c1 = acc[im][in][1] + b1;
            float c2 = acc[im][in][2] + b0;
            float c3 = acc[im][in][3] + b1;
            if (RELU) {
                c0 = c0 > 0.f ? c0 : 0.f;  c1 = c1 > 0.f ? c1 : 0.f;
                c2 = c2 > 0.f ? c2 : 0.f;  c3 = c3 > 0.f ? c3 : 0.f;
            }
            if (HOUT) {
                if (row < M) {
                    __half2 hv = __floats2half2_rn(c0, c1);
                    *(uint32_t*)&Chf[(size_t)row * Ntot + col] = *(uint32_t*)&hv;
                }
                if (row + 8 < M) {
                    __half2 hv = __floats2half2_rn(c2, c3);
                    *(uint32_t*)&Chf[(size_t)(row + 8) * Ntot + col] = *(uint32_t*)&hv;
                }
            } else {
                if (row < M)
                    *(float2*)&Cf[(size_t)row * Ntot + col] = make_float2(c0, c1);
                if (row + 8 < M)
                    *(float2*)&Cf[(size_t)(row + 8) * Ntot + col] = make_float2(c2, c3);
            }
        }
    }
}

// ---------------- small-N GEMM: CTA 128x32, warp 64x8 --------------------
// For latency-bound small levels: 4x more CTAs along N, 4x shorter critical
// path per CTA. fp32 output only, no bias/relu.
#define BTE_S 768       // 32*24
#define STGE_S 3840     // A tile + 32-row B tile

__global__ __launch_bounds__(256, 4) void gemm_s(
    const __half* __restrict__ A1, const __half* __restrict__ B1,
    const __half* __restrict__ A2, const __half* __restrict__ B2,
    float* __restrict__ Cf, int M, int Ntot)
{
    extern __shared__ uint16_t sm16[];
    const int t    = threadIdx.x;
    const int lane = t & 31, wid = t >> 5;
    const int q = lane >> 2, p = lane & 3;
    const int wm = wid >> 2, wn = wid & 3;       // warp tile 64x8
    const int bm = blockIdx.y * 128;
    const int bn = blockIdx.x * 32;

    const int r  = t >> 1;
    const int hf = t & 1;

    const int npass = (A2 != nullptr) ? 2 : 1;
    const int CT = npass * 32;

    float acc[4][4];
#pragma unroll
    for (int im = 0; im < 4; ++im)
#pragma unroll
        for (int k = 0; k < 4; ++k) acc[im][k] = 0.f;

    auto stage = [&](int cc) {
        const int pass = cc >> 5, k0 = (cc & 31) * 16;
        const __half* A = pass ? A2 : A1;
        const __half* B = pass ? B2 : B1;
        uint16_t* stg = sm16 + (cc & 3) * STGE_S;
        const bool pa = (bm + r < M);
        cp16z(stg + r * ASTR + hf * 8, A + (size_t)(bm + r) * 512 + k0 + hf * 8, pa);
        if (t < 64) {
            cp16z(stg + TE + r * ASTR + hf * 8,
                  B + (size_t)(bn + r) * 512 + k0 + hf * 8, true);
        }
    };

    stage(0); cp_commit();
    if (CT > 1) { stage(1); cp_commit(); }

    for (int c = 0; c < CT; ++c) {
        if (c + 2 < CT) stage(c + 2);
        cp_commit();
        cp_wait2();
        __syncthreads();

        const uint16_t* stg = sm16 + (c & 3) * STGE_S;
        const uint16_t* AT = stg;
        const uint16_t* BT = stg + TE;

        uint32_t bh[2];
        {
            int off = (wn * 8 + q) * ASTR + 2 * p;
            bh[0] = *(const uint32_t*)(BT + off);
            bh[1] = *(const uint32_t*)(BT + off + 8);
        }
#pragma unroll
        for (int im = 0; im < 4; ++im) {
            int off = (wm * 64 + im * 16 + q) * ASTR + 2 * p;
            uint32_t ah[4];
            ah[0] = *(const uint32_t*)(AT + off);
            ah[1] = *(const uint32_t*)(AT + off + 8 * ASTR);
            ah[2] = *(const uint32_t*)(AT + off + 8);
            ah[3] = *(const uint32_t*)(AT + off + 8 * ASTR + 8);
            mma_f16(acc[im], ah, bh);
        }
    }

#pragma unroll
    for (int im = 0; im < 4; ++im) {
        int row = bm + wm * 64 + im * 16 + q;
        int col = bn + wn * 8 + 2 * p;
        if (row < M)
            *(float2*)&Cf[(size_t)row * Ntot + col] = make_float2(acc[im][0], acc[im][1]);
        if (row + 8 < M)
            *(float2*)&Cf[(size_t)(row + 8) * Ntot + col] = make_float2(acc[im][2], acc[im][3]);
    }
}

// ---------------- conversions ---------------------------------------------
// One kernel for all weight transposes: W [512, Nc] fp32 -> [Nc, 512] fp16.
__global__ void conv_all(const float* __restrict__ W_in,
                         const float* __restrict__ W_ioux,
                         const float* __restrict__ W_iouh,
                         const float* __restrict__ W_fx,
                         const float* __restrict__ W_fh,
                         const float* __restrict__ W_out,
                         __half* __restrict__ wh)
{
    int idx = blockIdx.x * blockDim.x + threadIdx.x;
    const float* src; int Nc; __half* dst; int loc = idx;
    if      (loc < 262144)  { src = W_in;                Nc = 512;  dst = wh + OFF_WIN; }
    else if ((loc -= 262144) < 786432) { src = W_ioux;   Nc = 1536; dst = wh + OFF_CX0; }
    else if ((loc -= 786432) < 262144) { src = W_fx;     Nc = 512;  dst = wh + OFF_CX0 + FXROW; }
    else if ((loc -= 262144) < 786432) { src = W_ioux + 512 * 1536; Nc = 1536; dst = wh + OFF_CX1; }
    else if ((loc -= 786432) < 262144) { src = W_fx + 512 * 512;    Nc = 512;  dst = wh + OFF_CX1 + FXROW; }
    else if ((loc -= 262144) < 786432) { src = W_iouh;   Nc = 1536; dst = wh + OFF_CH0; }
    else if ((loc -= 786432) < 786432) { src = W_iouh + 512 * 1536; Nc = 1536; dst = wh + OFF_CH1; }
    else if ((loc -= 786432) < 262144) { src = W_fh;     Nc = 512;  dst = wh + OFF_FH0; }
    else if ((loc -= 262144) < 262144) { src = W_fh + 512 * 512;    Nc = 512;  dst = wh + OFF_FH1; }
    else if ((loc -= 262144) < 131072) { src = W_out;    Nc = 256;  dst = wh + OFF_WOUT; }
    else return;
    int n = loc >> 9, k = loc & 511;
    dst[loc] = __float2half(src[(size_t)k * Nc + n]);
}

__global__ void conv_x(const float* __restrict__ X, __half* __restrict__ Xh)
{
    size_t idx = (size_t)blockIdx.x * blockDim.x + threadIdx.x;
    if (idx >= (size_t)NN * HH) return;
    Xh[idx] = __float2half(X[idx]);
}

// ---------------- pointwise kernels (grouped: 4 rows/thread + hs) ---------
__device__ __forceinline__ float sigm(float x) { return 1.f / (1.f + expf(-x)); }

__global__ void leaf_pw_g(const float* __restrict__ iou,
                          const float* __restrict__ bix, const float* __restrict__ bih,
                          __half* __restrict__ H, float* __restrict__ cell,
                          __half* __restrict__ hs)
{
    int idx = blockIdx.x * blockDim.x + threadIdx.x;
    if (idx >= (NLEAF / 4) * HH) return;
    int rg = idx >> 9, j = idx & 511;
    float bi = bix[j]        + bih[j];
    float bo = bix[512 + j]  + bih[512 + j];
    float bu = bix[1024 + j] + bih[1024 + j];
    float hsv = 0.f;
#pragma unroll
    for (int k = 0; k < 4; ++k) {
        int r = 4 * rg + k;
        const float* row = iou + (size_t)r * 1536;
        float i = sigm (row[j]        + bi);
        float o = sigm (row[512 + j]  + bo);
        float u = tanhf(row[1024 + j] + bu);
        float c = i * u;
        size_t g = (size_t)(SLEAF + r) * HH + j;
        cell[g] = c;
        float hv = o * tanhf(c);
        H[g] = __float2half(hv);
        hsv += hv;
    }
    hs[(size_t)rg * HH + j] = __float2half(hsv);
}

// combined iou buffer row layout: [i|o|u|fx], stride 2048. n must be >= 4.
__global__ void int_pw_g(const float* __restrict__ cio, const float* __restrict__ fh,
                         const float* __restrict__ bix, const float* __restrict__ bih,
                         const float* __restrict__ bfx, const float* __restrict__ bfh,
                         __half* __restrict__ H, float* __restrict__ cell,
                         __half* __restrict__ hs,
                         int n, int s, int sc)
{
    int idx = blockIdx.x * blockDim.x + threadIdx.x;
    if (idx >= (n / 4) * HH) return;
    int rg = idx >> 9, j = idx & 511;
    float bi = bix[j]        + bih[j];
    float bo = bix[512 + j]  + bih[512 + j];
    float bu = bix[1024 + j] + bih[1024 + j];
    float bf = bfx[j] + bfh[j];
    float hsv = 0.f;
#pragma unroll
    for (int k = 0; k < 4; ++k) {
        int r = 4 * rg + k;
        const float* row = cio + (size_t)r * 2048;
        float i = sigm (row[j]        + bi);
        float o = sigm (row[512 + j]  + bo);
        float u = tanhf(row[1024 + j] + bu);
        float fxv = row[1536 + j] + bf;
        float acc = i * u;
#pragma unroll
        for (int kk = 0; kk < 4; ++kk) {
            float f = sigm(fxv + fh[(size_t)(4 * r + kk) * HH + j]);
            acc += f * cell[(size_t)(sc + 4 * r + kk) * HH + j];
        }
        size_t g = (size_t)(s + r) * HH + j;
        cell[g] = acc;
        float hv = o * tanhf(acc);
        H[g] = __float2half(hv);
        hsv += hv;
    }
    hs[(size_t)rg * HH + j] = __float2half(hsv);
}

// root level (n == 1): no hs output
__global__ void int_pw_root(const float* __restrict__ cio, const float* __restrict__ fh,
                            const float* __restrict__ bix, const float* __restrict__ bih,
                            const float* __restrict__ bfx, const float* __restrict__ bfh,
                            __half* __restrict__ H, float* __restrict__ cell)
{
    int j = blockIdx.x * blockDim.x + threadIdx.x;
    if (j >= HH) return;
    float i = sigm (cio[j]        + bix[j]        + bih[j]);
    float o = sigm (cio[512 + j]  + bix[512 + j]  + bih[512 + j]);
    float u = tanhf(cio[1024 + j] + bix[1024 + j] + bih[1024 + j]);
    float fxv = cio[1536 + j] + bfx[j] + bfh[j];
    float acc = i * u;
#pragma unroll
    for (int kk = 0; kk < 4; ++kk) {
        float f = sigm(fxv + fh[(size_t)kk * HH + j]);
        acc += f * cell[(size_t)(1 + kk) * HH + j];
    }
    cell[j] = acc;
    H[j] = __float2half(o * tanhf(acc));
}

__global__ void colsum_part(const __half* __restrict__ H, float* __restrict__ part)
{
    int b = blockIdx.x;
    const int rows_per = (NN + 511) / 512;
    int r0 = b * rows_per;
    int r1 = r0 + rows_per; if (r1 > NN) r1 = NN;
    for (int j = threadIdx.x; j < HH; j += blockDim.x) {
        float s = 0.f;
        for (int r = r0; r < r1; ++r) s += __half2float(H[(size_t)r * HH + j]);
        part[(size_t)b * HH + j] = s;
    }
}

__global__ void colsum_final(const float* __restrict__ part, float* __restrict__ cs)
{
    int j = blockIdx.x * blockDim.x + threadIdx.x;
    if (j >= HH) return;
    float acc = 0.f;
    for (int b = 0; b < 512; ++b) acc += part[(size_t)b * HH + j];
    cs[j] = acc;
}

__global__ void tree_kernel(const float* __restrict__ cs, const float* __restrict__ W_out,
                            const float* __restrict__ b_out, float* __restrict__ out)
{
    int j = threadIdx.x;
    float acc = (float)NN * b_out[j];
    for (int k = 0; k < HH; ++k) acc += cs[k] * W_out[(size_t)k * OUTF + j];
    out[j] = acc;
}

// ---------------- driver ---------------------------------------------------
static void* symv(const void* s) { void* p = nullptr; cudaGetSymbolAddress(&p, s); return p; }

extern "C" void kernel_launch(void* const* d_in, const int* in_sizes, int n_in,
                              void* d_out, int out_size)
{
    (void)in_sizes; (void)n_in; (void)out_size;
    const float* x      = (const float*)d_in[0];
    const float* W_in   = (const float*)d_in[8];
    const float* b_in   = (const float*)d_in[9];
    const float* W_ioux = (const float*)d_in[10];
    const float* b_ioux = (const float*)d_in[11];
    const float* W_iouh = (const float*)d_in[12];
    const float* b_iouh = (const float*)d_in[13];
    const float* W_fx   = (const float*)d_in[14];
    const float* b_fx   = (const float*)d_in[15];
    const float* W_fh   = (const float*)d_in[16];
    const float* b_fh   = (const float*)d_in[17];
    const float* W_out  = (const float*)d_in[18];
    const float* b_out  = (const float*)d_in[19];
    float* out = (float*)d_out;

    __half* wh  = (__half*)symv(g_wh);
    __half* xh  = (__half*)symv(g_x);
    __half* h0  = (__half*)symv(g_h0);
    __half* hi  = (__half*)symv(g_hi);
    __half* hs  = (__half*)symv(g_hs);
    float* cell = (float*)symv(g_cell);
    float* iou  = (float*)symv(g_iou);
    float* fh   = (float*)symv(g_fh);
    float* part = (float*)symv(g_part);
    float* cs   = (float*)symv(g_cs);

    const int SMB   = 4 * STGE * 2;     // 49152 B
    const int SMB_S = 4 * STGE_S * 2;   // 30720 B
    cudaFuncSetAttribute(gemm_mma<false,false>, cudaFuncAttributeMaxDynamicSharedMemorySize, SMB);
    cudaFuncSetAttribute(gemm_mma<true,true>,   cudaFuncAttributeMaxDynamicSharedMemorySize, SMB);

    // ---- conversions
    conv_all<<<(4587520 + 255) / 256, 256>>>(W_in, W_ioux, W_iouh, W_fx, W_fh, W_out, wh);
    cudaMemsetAsync(wh + OFF_CH0 + FXROW, 0, 512 * 512 * 2);
    cudaMemsetAsync(wh + OFF_CH1 + FXROW, 0, 512 * 512 * 2);
    conv_x<<<(int)(((size_t)NN * HH + 255) / 256), 256>>>(x, xh);

    const int MT_ALL = (NN + 127) / 128;   // 683

    // ---- input projection: h0 = relu(x @ W_in + b_in), fp16 out
    gemm_mma<true,true><<<dim3(4, MT_ALL), 256, SMB>>>(
        xh, wh + OFF_WIN, nullptr, nullptr,
        b_in, nullptr, h0, NN, HH);

    const int offCX[2] = {OFF_CX0, OFF_CX1};
    const int offCH[2] = {OFF_CH0, OFF_CH1};
    const int offFH[2] = {OFF_FH0, OFF_FH1};

    for (int l = 0; l < 2; ++l) {
        __half* hin  = (l == 0) ? h0 : hi;
        __half* hout = (l == 0) ? hi : h0;
        const float* Bix = b_ioux + (size_t)l * 1536;
        const float* Bih = b_iouh + (size_t)l * 1536;
        const float* Bfx = b_fx   + (size_t)l * HH;
        const float* Bfh = b_fh   + (size_t)l * HH;

        // leaf level: iou only (rows 0..1535 of CX = W_ioux), stride 1536
        gemm_mma<false,false><<<dim3(12, NLEAF / 128), 256, SMB>>>(
            hin + (size_t)SLEAF * HH, wh + offCX[l],
            nullptr, nullptr,
            nullptr, iou, nullptr, NLEAF, 1536);
        // leaf pointwise (also emits hs for level 7)
        leaf_pw_g<<<((NLEAF / 4) * HH) / 256, 256>>>(iou, Bix, Bih, hout, cell, hs);

        for (int d = 7; d >= 0; --d) {
            int s  = LS[d];
            int n  = LS[d + 1] - LS[d];
            int sc = LS[d + 1];
            int mt  = (n + 127) / 128;
            int mt4 = (4 * n + 127) / 128;

            // dual GEMM: C[n,2048] = hin@[Wix|Wfx] + hs@[Wih|0]
            if (n >= 4096) {
                gemm_mma<false,false><<<dim3(16, mt), 256, SMB>>>(
                    hin + (size_t)s * HH, wh + offCX[l],
                    hs, wh + offCH[l],
                    nullptr, iou, nullptr, n, 2048);
            } else {
                gemm_s<<<dim3(64, mt), 256, SMB_S>>>(
                    hin + (size_t)s * HH, wh + offCX[l],
                    hs, wh + offCH[l], iou, n, 2048);
            }
            // fh GEMM: [4n,512] = children_H @ W_fh
            if (n >= 1024) {
                gemm_mma<false,false><<<dim3(4, mt4), 256, SMB>>>(
                    hout + (size_t)sc * HH, wh + offFH[l],
                    nullptr, nullptr,
                    nullptr, fh, nullptr, 4 * n, HH);
            } else {
                gemm_s<<<dim3(16, mt4), 256, SMB_S>>>(
                    hout + (size_t)sc * HH, wh + offFH[l],
                    nullptr, nullptr, fh, 4 * n, HH);
            }
            // pointwise (emits hs for level d-1); root handled separately
            if (d > 0) {
                int nblk = ((n / 4) * HH + 255) / 256;
                int_pw_g<<<nblk, 256>>>(iou, fh, Bix, Bih, Bfx, Bfh,
                                        hout, cell, hs, n, s, sc);
            } else {
                int_pw_root<<<2, 256>>>(iou, fh, Bix, Bih, Bfx, Bfh, hout, cell);
            }
        }
    }

    // node_emb = h0 @ W_out + b_out
    gemm_mma<false,false><<<dim3(2, MT_ALL), 256, SMB>>>(
        h0, wh + OFF_WOUT, nullptr, nullptr,
        b_out, out, nullptr, NN, OUTF);

    // tree_emb
    colsum_part<<<512, 256>>>(h0, part);
    colsum_final<<<2, 256>>>(part, cs);
    tree_kernel<<<1, 256>>>(cs, W_out, b_out, out + (size_t)NN * OUTF);
}